// round 13
// baseline (speedup 1.0000x reference)
#include <cuda_runtime.h>
#include <cuda_bf16.h>
#include <cstdint>

#define D_MODEL   1024
#define NUM_HEADS 16
#define D_K       64
#define BATCH     4
#define SEQ       2048
#define M_TOKENS  (BATCH * SEQ)          // 8192
#define NELEM     (M_TOKENS * D_MODEL)   // 8388608
#define W_ELEM    (D_MODEL * D_MODEL)    // 1048576

// ---------------------------------------------------------------------------
// Scratch (allocation-free)
// ---------------------------------------------------------------------------
__device__ __nv_bfloat16 g_xhi[NELEM],  g_xlo[NELEM];
__device__ __nv_bfloat16 g_wqhi[W_ELEM], g_wqlo[W_ELEM];
__device__ __nv_bfloat16 g_wkhi[W_ELEM], g_wklo[W_ELEM];
__device__ __nv_bfloat16 g_wvhi[W_ELEM], g_wvlo[W_ELEM];
__device__ __nv_bfloat16 g_wohi[W_ELEM], g_wolo[W_ELEM];
__device__ __nv_bfloat16 g_qhi[NELEM],  g_qlo[NELEM];    // [b,h,s,d], pre-scaled
__device__ __nv_bfloat16 g_khi[NELEM],  g_klo[NELEM];    // [b,h,s,d]
__device__ __nv_bfloat16 g_vthi[NELEM], g_vtlo[NELEM];   // [b,h,d,s] (transposed)
__device__ __nv_bfloat16 g_ohi[NELEM],  g_olo[NELEM];    // [tok, 1024]

// ---------------------------------------------------------------------------
// helpers
// ---------------------------------------------------------------------------
__device__ __forceinline__ void mma16816(float* c, const uint32_t* a,
                                         const uint32_t* b)
{
    asm volatile(
        "mma.sync.aligned.m16n8k16.row.col.f32.bf16.bf16.f32 "
        "{%0,%1,%2,%3}, {%4,%5,%6,%7}, {%8,%9}, {%0,%1,%2,%3};"
        : "+f"(c[0]), "+f"(c[1]), "+f"(c[2]), "+f"(c[3])
        : "r"(a[0]), "r"(a[1]), "r"(a[2]), "r"(a[3]),
          "r"(b[0]), "r"(b[1]));
}
__device__ __forceinline__ void ldsm_x4(uint32_t& r0, uint32_t& r1,
                                        uint32_t& r2, uint32_t& r3,
                                        uint32_t addr)
{
    asm volatile("ldmatrix.sync.aligned.m8n8.x4.shared.b16 {%0,%1,%2,%3}, [%4];"
                 : "=r"(r0), "=r"(r1), "=r"(r2), "=r"(r3) : "r"(addr));
}
__device__ __forceinline__ uint32_t smem_u32(const void* p) {
    uint32_t a;
    asm("{ .reg .u64 t; cvta.to.shared.u64 t, %1; cvt.u32.u64 %0, t; }"
        : "=r"(a) : "l"(p));
    return a;
}
__device__ __forceinline__ void cp_async16(uint32_t dst, const void* src) {
    asm volatile("cp.async.cg.shared.global [%0], [%1], 16;"
                 :: "r"(dst), "l"(src) : "memory");
}
__device__ __forceinline__ void cp_commit() {
    asm volatile("cp.async.commit_group;" ::: "memory");
}
template <int N>
__device__ __forceinline__ void cp_wait() {
    asm volatile("cp.async.wait_group %0;" :: "n"(N) : "memory");
}
// split (x,y) into packed bf16 hi pair and bf16 lo pair
__device__ __forceinline__ void split2(float x, float y,
                                       uint32_t& hi, uint32_t& lo) {
    __nv_bfloat16 hx = __float2bfloat16(x);
    __nv_bfloat16 hy = __float2bfloat16(y);
    __nv_bfloat16 lx = __float2bfloat16(x - __bfloat162float(hx));
    __nv_bfloat16 ly = __float2bfloat16(y - __bfloat162float(hy));
    hi = (uint32_t)__bfloat16_as_ushort(hx) |
         ((uint32_t)__bfloat16_as_ushort(hy) << 16);
    lo = (uint32_t)__bfloat16_as_ushort(lx) |
         ((uint32_t)__bfloat16_as_ushort(ly) << 16);
}

// ---------------------------------------------------------------------------
// fp32 -> (bf16 hi, bf16 lo) split: x (single tensor)
// ---------------------------------------------------------------------------
__global__ void prep_split(const float* __restrict__ in,
                           __nv_bfloat16* __restrict__ hi,
                           __nv_bfloat16* __restrict__ lo, int n4)
{
    int i = blockIdx.x * blockDim.x + threadIdx.x;
    if (i >= n4) return;
    float4 f = ((const float4*)in)[i];
    float fv[4] = {f.x, f.y, f.z, f.w};
    __nv_bfloat16 h[4], l[4];
#pragma unroll
    for (int j = 0; j < 4; ++j) {
        h[j] = __float2bfloat16(fv[j]);
        l[j] = __float2bfloat16(fv[j] - __bfloat162float(h[j]));
    }
    ((uint2*)hi)[i] = *(uint2*)h;
    ((uint2*)lo)[i] = *(uint2*)l;
}

// All 4 weight matrices in one launch: grid (W_ELEM/4/256, 4)
__global__ void prep_split_w4(
    const float* __restrict__ wq, const float* __restrict__ wk,
    const float* __restrict__ wv, const float* __restrict__ wo,
    __nv_bfloat16* __restrict__ qh, __nv_bfloat16* __restrict__ ql,
    __nv_bfloat16* __restrict__ kh, __nv_bfloat16* __restrict__ kl,
    __nv_bfloat16* __restrict__ vh, __nv_bfloat16* __restrict__ vl,
    __nv_bfloat16* __restrict__ oh, __nv_bfloat16* __restrict__ ol)
{
    int i = blockIdx.x * blockDim.x + threadIdx.x;
    const float* in;
    __nv_bfloat16 *hi, *lo;
    if      (blockIdx.y == 0) { in = wq; hi = qh; lo = ql; }
    else if (blockIdx.y == 1) { in = wk; hi = kh; lo = kl; }
    else if (blockIdx.y == 2) { in = wv; hi = vh; lo = vl; }
    else                      { in = wo; hi = oh; lo = ol; }
    float4 f = ((const float4*)in)[i];
    float fv[4] = {f.x, f.y, f.z, f.w};
    __nv_bfloat16 h[4], l[4];
#pragma unroll
    for (int j = 0; j < 4; ++j) {
        h[j] = __float2bfloat16(fv[j]);
        l[j] = __float2bfloat16(fv[j] - __bfloat162float(h[j]));
    }
    ((uint2*)hi)[i] = *(uint2*)h;
    ((uint2*)lo)[i] = *(uint2*)l;
}

// ---------------------------------------------------------------------------
// HMMA GEMM (hi/lo 3-product). CTA 128x128, BK=32, 256 threads, 2 CTAs/SM.
// ldmatrix.x4 fragment loads. Unchanged from round 12.
// ---------------------------------------------------------------------------
#define BK        32
#define SROW      40
#define TILE_B    (128 * SROW * 2)
#define STAGE_B   (4 * TILE_B)
#define GEMM_SMEM (2 * STAGE_B)
#define NK_CHUNKS (D_MODEL / BK)

__global__ __launch_bounds__(256, 2)
void gemm_tc(const __nv_bfloat16* __restrict__ Ahi,
             const __nv_bfloat16* __restrict__ Alo,
             const __nv_bfloat16* __restrict__ B0h,
             const __nv_bfloat16* __restrict__ B0l,
             const __nv_bfloat16* __restrict__ B1h,
             const __nv_bfloat16* __restrict__ B1l,
             const __nv_bfloat16* __restrict__ B2h,
             const __nv_bfloat16* __restrict__ B2l,
             float* __restrict__ C,
             __nv_bfloat16* __restrict__ C0h, __nv_bfloat16* __restrict__ C0l,
             __nv_bfloat16* __restrict__ C1h, __nv_bfloat16* __restrict__ C1l,
             __nv_bfloat16* __restrict__ C2h, __nv_bfloat16* __restrict__ C2l,
             int fused)
{
    extern __shared__ __align__(16) char sm[];

    const int mode = fused ? ((int)blockIdx.z + 1) : 0;
    const __nv_bfloat16 *Bhi, *Blo;
    __nv_bfloat16 *Chi = nullptr, *Clo = nullptr;
    if (!fused || blockIdx.z == 0) { Bhi = B0h; Blo = B0l; Chi = C0h; Clo = C0l; }
    else if (blockIdx.z == 1)      { Bhi = B1h; Blo = B1l; Chi = C1h; Clo = C1l; }
    else                           { Bhi = B2h; Blo = B2l; Chi = C2h; Clo = C2l; }

    const int tid  = threadIdx.x;
    const int wid  = tid >> 5;
    const int lane = tid & 31;
    const int grp  = lane >> 2;
    const int qp   = lane & 3;
    const int lrow = lane & 7;
    const int mat  = lane >> 3;          // 0..3 (ldmatrix address group)

    const int warp_m = (wid & 1) * 64;
    const int warp_n = (wid >> 1) * 32;

    // ldmatrix per-lane address components (elements)
    const int a_row = warp_m + (mat & 1) * 8 + lrow;   // + mf*16
    const int a_col = (mat >> 1) * 8;                  // + kb
    const int b_row = warp_n + (mat >> 1) * 8 + lrow;  // + nfp*16
    const int b_col = (mat & 1) * 8;                   // + kb

    const int m0 = blockIdx.y * 128;
    const int n0 = blockIdx.x * 128;

    const __nv_bfloat16* srcs[4] = {
        Ahi + (size_t)m0 * D_MODEL, Alo + (size_t)m0 * D_MODEL,
        Bhi + (size_t)n0 * D_MODEL, Blo + (size_t)n0 * D_MODEL
    };

    const uint32_t smbase = smem_u32(sm);

    auto load_stage = [&](int stage, int k0) {
        uint32_t dst0 = smbase + stage * STAGE_B;
#pragma unroll
        for (int a = 0; a < 4; ++a) {
#pragma unroll
            for (int it = 0; it < 2; ++it) {
                int g   = tid + it * 256;
                int row = g >> 2;
                int q   = g & 3;
                const __nv_bfloat16* src = srcs[a] + (size_t)row * D_MODEL + k0 + q * 8;
                cp_async16(dst0 + a * TILE_B + (row * SROW + q * 8) * 2, src);
            }
        }
        cp_commit();
    };

    float acc[4][4][4];
#pragma unroll
    for (int mf = 0; mf < 4; ++mf)
#pragma unroll
        for (int nf = 0; nf < 4; ++nf)
#pragma unroll
            for (int r = 0; r < 4; ++r) acc[mf][nf][r] = 0.0f;

    load_stage(0, 0);
    load_stage(1, BK);

    for (int kc = 0; kc < NK_CHUNKS; ++kc) {
        if (kc < NK_CHUNKS - 2) cp_wait<1>();
        else                    cp_wait<0>();
        __syncthreads();

        const int st = kc & 1;
        const uint32_t ah_base = smbase + st * STAGE_B;
        const uint32_t al_base = ah_base + TILE_B;
        const uint32_t bh_base = ah_base + 2 * TILE_B;
        const uint32_t bl_base = ah_base + 3 * TILE_B;

#pragma unroll
        for (int ks = 0; ks < 2; ++ks) {
            const int kb = ks * 16;
            // B fragments: 2 x4-LDSM per precision (4 nf x 2 regs)
            uint32_t bhi[4][2], blo[4][2];
#pragma unroll
            for (int nfp = 0; nfp < 2; ++nfp) {
                uint32_t off = (uint32_t)(((b_row + nfp * 16) * SROW + b_col + kb) * 2);
                ldsm_x4(bhi[2*nfp][0], bhi[2*nfp][1],
                        bhi[2*nfp+1][0], bhi[2*nfp+1][1], bh_base + off);
                ldsm_x4(blo[2*nfp][0], blo[2*nfp][1],
                        blo[2*nfp+1][0], blo[2*nfp+1][1], bl_base + off);
            }
            // A fragments per-mf: 2 x4-LDSM, then 12 MMAs
#pragma unroll
            for (int mf = 0; mf < 4; ++mf) {
                uint32_t off = (uint32_t)(((a_row + mf * 16) * SROW + a_col + kb) * 2);
                uint32_t ah[4], al[4];
                ldsm_x4(ah[0], ah[1], ah[2], ah[3], ah_base + off);
                ldsm_x4(al[0], al[1], al[2], al[3], al_base + off);
#pragma unroll
                for (int nf = 0; nf < 4; ++nf) {
                    mma16816(acc[mf][nf], ah, bhi[nf]);
                    mma16816(acc[mf][nf], ah, blo[nf]);
                    mma16816(acc[mf][nf], al, bhi[nf]);
                }
            }
        }
        __syncthreads();
        if (kc + 2 < NK_CHUNKS) load_stage(st, (kc + 2) * BK);
    }

    // Epilogue
    const float scale = (mode == 1) ? 0.125f : 1.0f;
#pragma unroll
    for (int mf = 0; mf < 4; ++mf) {
#pragma unroll
        for (int half = 0; half < 2; ++half) {
            int m = m0 + warp_m + mf * 16 + grp + half * 8;
            int b = m >> 11, s = m & (SEQ - 1);
#pragma unroll
            for (int nf = 0; nf < 4; ++nf) {
                int n = n0 + warp_n + nf * 8 + qp * 2;
                float vx = acc[mf][nf][half * 2];
                float vy = acc[mf][nf][half * 2 + 1];
                if (mode == 0) {
                    *(float2*)&C[(size_t)m * D_MODEL + n] = make_float2(vx, vy);
                } else {
                    int h = n >> 6, d = n & 63;
                    vx *= scale; vy *= scale;
                    uint32_t hp, lp;
                    split2(vx, vy, hp, lp);
                    if (mode != 3) {
                        size_t base = ((size_t)(b * NUM_HEADS + h) * SEQ + s) * D_K + d;
                        *(uint32_t*)&Chi[base] = hp;
                        *(uint32_t*)&Clo[base] = lp;
                    } else {
                        size_t base = ((size_t)(b * NUM_HEADS + h) * D_K + d) * SEQ + s;
                        Chi[base]        = __ushort_as_bfloat16((uint16_t)hp);
                        Clo[base]        = __ushort_as_bfloat16((uint16_t)lp);
                        Chi[base + SEQ]  = __ushort_as_bfloat16((uint16_t)(hp >> 16));
                        Clo[base + SEQ]  = __ushort_as_bfloat16((uint16_t)(lp >> 16));
                    }
                }
            }
        }
    }
}

// ---------------------------------------------------------------------------
// HMMA flash attention (causal, online softmax, bf16 hi/lo 3-product).
// 256 threads (8 warps), BM=128 (16 rows/warp), BN=32 key tiles.
// Register-lean (sacc/P-packs halved) + launch_bounds(256,2): 2 CTAs/SM so
// one CTA's softmax/shfl/sync latency is hidden by the other's MMA stream.
// K tiles [32 keys][64 d] stride 72; Vt tiles [64 d][32 keys] stride 40.
// ---------------------------------------------------------------------------
#define KROW     72                          // 64 + 8 pad (bf16)
#define VROW     40                          // 32 + 8 pad (bf16)
#define KTILE    (32 * KROW)                 // 2304 elems
#define VTILE    (64 * VROW)                 // 2560 elems
#define FSTAGE   (2 * KTILE + 2 * VTILE)     // 9728 elems
#define FA_SMEM  (2 * FSTAGE * 2)            // 38912 bytes

__global__ __launch_bounds__(256, 2)
void flash_tc(const __nv_bfloat16* __restrict__ qhi,
              const __nv_bfloat16* __restrict__ qlo,
              const __nv_bfloat16* __restrict__ khi,
              const __nv_bfloat16* __restrict__ klo,
              const __nv_bfloat16* __restrict__ vthi,
              const __nv_bfloat16* __restrict__ vtlo,
              __nv_bfloat16* __restrict__ ohi,
              __nv_bfloat16* __restrict__ olo)
{
    extern __shared__ __align__(16) __nv_bfloat16 fs[];

    const int tid  = threadIdx.x;
    const int w    = tid >> 5;               // 0..7
    const int lane = tid & 31;
    const int grp  = lane >> 2;
    const int qp   = lane & 3;

    const int bh = blockIdx.y;
    const int b  = bh >> 4;
    const int h  = bh & 15;
    const int i0 = blockIdx.x * 128;         // query tile start (128 rows)

    // Q fragments (pre-scaled by 0.125 in gemm_tc mode 1); warp rows i0+w*16..
    uint32_t qhf[4][4], qlf[4][4];
    {
        const __nv_bfloat16* qh = qhi + ((size_t)bh * SEQ + i0 + w * 16) * D_K;
        const __nv_bfloat16* ql = qlo + ((size_t)bh * SEQ + i0 + w * 16) * D_K;
#pragma unroll
        for (int kf = 0; kf < 4; ++kf) {
            int c0 = kf * 16 + qp * 2;
            qhf[kf][0] = *(const uint32_t*)&qh[grp * D_K + c0];
            qhf[kf][1] = *(const uint32_t*)&qh[(grp + 8) * D_K + c0];
            qhf[kf][2] = *(const uint32_t*)&qh[grp * D_K + c0 + 8];
            qhf[kf][3] = *(const uint32_t*)&qh[(grp + 8) * D_K + c0 + 8];
            qlf[kf][0] = *(const uint32_t*)&ql[grp * D_K + c0];
            qlf[kf][1] = *(const uint32_t*)&ql[(grp + 8) * D_K + c0];
            qlf[kf][2] = *(const uint32_t*)&ql[grp * D_K + c0 + 8];
            qlf[kf][3] = *(const uint32_t*)&ql[(grp + 8) * D_K + c0 + 8];
        }
    }

    const uint32_t smbase = smem_u32(fs);

    // One 32-key stage: Kh[32x64], Kl[32x64], Vh[64x32], Vl[64x32].
    // 1024 16B-chunks total, 4 iterations of 256 threads.
    auto load_kv = [&](int stage, int j0) {
        uint32_t dstb = smbase + stage * FSTAGE * 2;
#pragma unroll
        for (int t4 = 0; t4 < 4; ++t4) {
            int c    = tid + t4 * 256;       // 0..1023
            int tile = c >> 8;               // 0..3
            int idx  = c & 255;
            const __nv_bfloat16* sp;
            uint32_t doff;
            if (tile < 2) {                  // K tiles: row=idx>>3 (0..31), c8=idx&7
                int row = idx >> 3, c8 = idx & 7;
                sp = (tile == 0 ? khi : klo)
                     + ((size_t)bh * SEQ + j0 + row) * D_K + c8 * 8;
                doff = (uint32_t)((tile * KTILE + row * KROW + c8 * 8) * 2);
            } else {                         // V tiles: row=idx>>2 (0..63), c4=idx&3
                int row = idx >> 2, c4 = idx & 3;
                sp = (tile == 2 ? vthi : vtlo)
                     + ((size_t)bh * D_K + row) * SEQ + j0 + c4 * 8;
                doff = (uint32_t)((2 * KTILE + (tile - 2) * VTILE
                                   + row * VROW + c4 * 8) * 2);
            }
            cp_async16(dstb + doff, sp);
        }
        cp_commit();
    };

    float oacc[8][4];
#pragma unroll
    for (int nf = 0; nf < 8; ++nf)
#pragma unroll
        for (int r = 0; r < 4; ++r) oacc[nf][r] = 0.0f;
    float m0v = -1e30f, m1v = -1e30f, l0 = 0.0f, l1 = 0.0f;

    const int nt = i0 / 32 + 4;              // key tiles j0 = 0 .. i0+96
    load_kv(0, 0);

    for (int t = 0; t < nt; ++t) {
        const int st = t & 1;
        const int j0 = t * 32;
        if (t + 1 < nt) { load_kv(st ^ 1, (t + 1) * 32); cp_wait<1>(); }
        else            { cp_wait<0>(); }
        __syncthreads();

        const __nv_bfloat16* Kh = fs + st * FSTAGE;
        const __nv_bfloat16* Kl = Kh + KTILE;
        const __nv_bfloat16* Vh = Kh + 2 * KTILE;
        const __nv_bfloat16* Vl = Vh + VTILE;

        // S = Q K^T (32 keys -> sacc[4][4])
        float sacc[4][4];
#pragma unroll
        for (int nf = 0; nf < 4; ++nf)
#pragma unroll
            for (int r = 0; r < 4; ++r) sacc[nf][r] = 0.0f;

#pragma unroll
        for (int nf = 0; nf < 4; ++nf) {
            const int rb = (nf * 8 + grp) * KROW;
#pragma unroll
            for (int kf = 0; kf < 4; ++kf) {
                const int cc = kf * 16 + qp * 2;
                uint32_t bkh[2] = { *(const uint32_t*)&Kh[rb + cc],
                                    *(const uint32_t*)&Kh[rb + cc + 8] };
                uint32_t bkl[2] = { *(const uint32_t*)&Kl[rb + cc],
                                    *(const uint32_t*)&Kl[rb + cc + 8] };
                mma16816(sacc[nf], qhf[kf], bkh);
                mma16816(sacc[nf], qhf[kf], bkl);
                mma16816(sacc[nf], qlf[kf], bkh);
            }
        }

        // causal mask (any tile overlapping this warp's rows; warp-uniform test)
        if (j0 + 32 > i0 + w * 16) {
            const int grow0 = i0 + w * 16 + grp;
#pragma unroll
            for (int nf = 0; nf < 4; ++nf) {
                int gc = j0 + nf * 8 + qp * 2;
                if (gc     > grow0)     sacc[nf][0] = -1e30f;
                if (gc + 1 > grow0)     sacc[nf][1] = -1e30f;
                if (gc     > grow0 + 8) sacc[nf][2] = -1e30f;
                if (gc + 1 > grow0 + 8) sacc[nf][3] = -1e30f;
            }
        }

        // row max (own 8 + quad shfl)
        float mx0 = -1e30f, mx1 = -1e30f;
#pragma unroll
        for (int nf = 0; nf < 4; ++nf) {
            mx0 = fmaxf(mx0, fmaxf(sacc[nf][0], sacc[nf][1]));
            mx1 = fmaxf(mx1, fmaxf(sacc[nf][2], sacc[nf][3]));
        }
        mx0 = fmaxf(mx0, __shfl_xor_sync(0xffffffffu, mx0, 1));
        mx0 = fmaxf(mx0, __shfl_xor_sync(0xffffffffu, mx0, 2));
        mx1 = fmaxf(mx1, __shfl_xor_sync(0xffffffffu, mx1, 1));
        mx1 = fmaxf(mx1, __shfl_xor_sync(0xffffffffu, mx1, 2));

        float mn0 = fmaxf(m0v, mx0), mn1 = fmaxf(m1v, mx1);
        float a0 = __expf(m0v - mn0), a1 = __expf(m1v - mn1);
        m0v = mn0; m1v = mn1;

        // P = exp(S - m), split hi/lo, packed as A-fragments
        float s0 = 0.0f, s1 = 0.0f;
        uint32_t ph01[4], ph23[4], pl01[4], pl23[4];
#pragma unroll
        for (int nf = 0; nf < 4; ++nf) {
            float p0 = __expf(sacc[nf][0] - mn0);
            float p1 = __expf(sacc[nf][1] - mn0);
            float p2 = __expf(sacc[nf][2] - mn1);
            float p3 = __expf(sacc[nf][3] - mn1);
            s0 += p0 + p1; s1 += p2 + p3;
            split2(p0, p1, ph01[nf], pl01[nf]);
            split2(p2, p3, ph23[nf], pl23[nf]);
        }
        s0 += __shfl_xor_sync(0xffffffffu, s0, 1);
        s0 += __shfl_xor_sync(0xffffffffu, s0, 2);
        s1 += __shfl_xor_sync(0xffffffffu, s1, 1);
        s1 += __shfl_xor_sync(0xffffffffu, s1, 2);
        l0 = l0 * a0 + s0;
        l1 = l1 * a1 + s1;

#pragma unroll
        for (int nf = 0; nf < 8; ++nf) {
            oacc[nf][0] *= a0; oacc[nf][1] *= a0;
            oacc[nf][2] *= a1; oacc[nf][3] *= a1;
        }

        // O += P V   (Vt tiles: [d][j], NT pattern; K=32 keys -> kf 0..1)
#pragma unroll
        for (int nfd = 0; nfd < 8; ++nfd) {
            const int rb = (nfd * 8 + grp) * VROW;
#pragma unroll
            for (int kf = 0; kf < 2; ++kf) {
                const int cc = kf * 16 + qp * 2;
                uint32_t bvh[2] = { *(const uint32_t*)&Vh[rb + cc],
                                    *(const uint32_t*)&Vh[rb + cc + 8] };
                uint32_t bvl[2] = { *(const uint32_t*)&Vl[rb + cc],
                                    *(const uint32_t*)&Vl[rb + cc + 8] };
                uint32_t ap[4] = { ph01[2 * kf], ph23[2 * kf],
                                   ph01[2 * kf + 1], ph23[2 * kf + 1] };
                uint32_t al[4] = { pl01[2 * kf], pl23[2 * kf],
                                   pl01[2 * kf + 1], pl23[2 * kf + 1] };
                mma16816(oacc[nfd], ap, bvh);
                mma16816(oacc[nfd], ap, bvl);
                mma16816(oacc[nfd], al, bvh);
            }
        }
        __syncthreads();
    }

    // epilogue: normalize, split hi/lo, write merged [tok, h*64+d]
    const float il0 = 1.0f / l0, il1 = 1.0f / l1;
    const size_t tok0 = (size_t)b * SEQ + i0 + w * 16 + grp;
#pragma unroll
    for (int nf = 0; nf < 8; ++nf) {
        int col = h * D_K + nf * 8 + qp * 2;
        uint32_t hp, lp;
        split2(oacc[nf][0] * il0, oacc[nf][1] * il0, hp, lp);
        *(uint32_t*)&ohi[tok0 * D_MODEL + col] = hp;
        *(uint32_t*)&olo[tok0 * D_MODEL + col] = lp;
        split2(oacc[nf][2] * il1, oacc[nf][3] * il1, hp, lp);
        *(uint32_t*)&ohi[(tok0 + 8) * D_MODEL + col] = hp;
        *(uint32_t*)&olo[(tok0 + 8) * D_MODEL + col] = lp;
    }
}

// ---------------------------------------------------------------------------
// Launch
// ---------------------------------------------------------------------------
extern "C" void kernel_launch(void* const* d_in, const int* in_sizes, int n_in,
                              void* d_out, int out_size)
{
    const float* x  = (const float*)d_in[0];
    const float* wq = (const float*)d_in[1];
    const float* wk = (const float*)d_in[2];
    const float* wv = (const float*)d_in[3];
    const float* wo = (const float*)d_in[4];
    float* out = (float*)d_out;

    __nv_bfloat16 *xhi, *xlo, *wqhi, *wqlo, *wkhi, *wklo, *wvhi, *wvlo,
                  *wohi, *wolo, *qhi, *qlo, *khi, *klo, *vthi, *vtlo,
                  *ohi, *olo;
    cudaGetSymbolAddress((void**)&xhi, g_xhi);
    cudaGetSymbolAddress((void**)&xlo, g_xlo);
    cudaGetSymbolAddress((void**)&wqhi, g_wqhi);
    cudaGetSymbolAddress((void**)&wqlo, g_wqlo);
    cudaGetSymbolAddress((void**)&wkhi, g_wkhi);
    cudaGetSymbolAddress((void**)&wklo, g_wklo);
    cudaGetSymbolAddress((void**)&wvhi, g_wvhi);
    cudaGetSymbolAddress((void**)&wvlo, g_wvlo);
    cudaGetSymbolAddress((void**)&wohi, g_wohi);
    cudaGetSymbolAddress((void**)&wolo, g_wolo);
    cudaGetSymbolAddress((void**)&qhi, g_qhi);
    cudaGetSymbolAddress((void**)&qlo, g_qlo);
    cudaGetSymbolAddress((void**)&khi, g_khi);
    cudaGetSymbolAddress((void**)&klo, g_klo);
    cudaGetSymbolAddress((void**)&vthi, g_vthi);
    cudaGetSymbolAddress((void**)&vtlo, g_vtlo);
    cudaGetSymbolAddress((void**)&ohi, g_ohi);
    cudaGetSymbolAddress((void**)&olo, g_olo);

    cudaFuncSetAttribute(gemm_tc, cudaFuncAttributeMaxDynamicSharedMemorySize,
                         GEMM_SMEM);
    cudaFuncSetAttribute(flash_tc, cudaFuncAttributeMaxDynamicSharedMemorySize,
                         FA_SMEM);

    prep_split<<<NELEM / 4 / 256, 256>>>(x, xhi, xlo, NELEM / 4);
    dim3 wGrid(W_ELEM / 4 / 256, 4);                 // (1024, 4)
    prep_split_w4<<<wGrid, 256>>>(wq, wk, wv, wo,
                                  wqhi, wqlo, wkhi, wklo,
                                  wvhi, wvlo, wohi, wolo);

    // Fused Q/K/V projections: grid.z selects weight + epilogue
    dim3 qkvGrid(D_MODEL / 128, M_TOKENS / 128, 3);  // (8, 64, 3)
    gemm_tc<<<qkvGrid, 256, GEMM_SMEM>>>(
        xhi, xlo,
        wqhi, wqlo, wkhi, wklo, wvhi, wvlo,
        nullptr,
        qhi, qlo, khi, klo, vthi, vtlo, 1);

    dim3 attnGrid(SEQ / 128, BATCH * NUM_HEADS);     // (16, 64)
    flash_tc<<<attnGrid, 256, FA_SMEM>>>(qhi, qlo, khi, klo, vthi, vtlo,
                                         ohi, olo);

    // Output projection (mode 0)
    dim3 oGrid(D_MODEL / 128, M_TOKENS / 128, 1);    // (8, 64)
    gemm_tc<<<oGrid, 256, GEMM_SMEM>>>(
        ohi, olo,
        wohi, wolo, wohi, wolo, wohi, wolo,
        out,
        nullptr, nullptr, nullptr, nullptr, nullptr, nullptr, 0);
}

// round 14
// speedup vs baseline: 1.1225x; 1.1225x over previous
#include <cuda_runtime.h>
#include <cuda_bf16.h>
#include <cuda_fp16.h>
#include <cstdint>

#define D_MODEL   1024
#define NUM_HEADS 16
#define D_K       64
#define BATCH     4
#define SEQ       2048
#define M_TOKENS  (BATCH * SEQ)          // 8192
#define NELEM     (M_TOKENS * D_MODEL)   // 8388608
#define W_ELEM    (D_MODEL * D_MODEL)    // 1048576

// ---------------------------------------------------------------------------
// Scratch (allocation-free)
// ---------------------------------------------------------------------------
__device__ __nv_bfloat16 g_xhi[NELEM],  g_xlo[NELEM];
__device__ __nv_bfloat16 g_wqhi[W_ELEM], g_wqlo[W_ELEM];
__device__ __nv_bfloat16 g_wkhi[W_ELEM], g_wklo[W_ELEM];
__device__ __nv_bfloat16 g_wvhi[W_ELEM], g_wvlo[W_ELEM];
__device__ __nv_bfloat16 g_wohi[W_ELEM], g_wolo[W_ELEM];
__device__ __half g_qh[NELEM];                         // Q fp16 [b,h,s,d], pre-scaled
__device__ __half g_kh[NELEM],  g_kl[NELEM];           // K fp16 hi/lo [b,h,s,d]
__device__ __half g_vth[NELEM], g_vtl[NELEM];          // V fp16 hi/lo [b,h,d,s]
__device__ __nv_bfloat16 g_ohi[NELEM],  g_olo[NELEM];  // attn out bf16 hi/lo [tok,1024]

// ---------------------------------------------------------------------------
// helpers
// ---------------------------------------------------------------------------
__device__ __forceinline__ void mma16816(float* c, const uint32_t* a,
                                         const uint32_t* b)
{
    asm volatile(
        "mma.sync.aligned.m16n8k16.row.col.f32.bf16.bf16.f32 "
        "{%0,%1,%2,%3}, {%4,%5,%6,%7}, {%8,%9}, {%0,%1,%2,%3};"
        : "+f"(c[0]), "+f"(c[1]), "+f"(c[2]), "+f"(c[3])
        : "r"(a[0]), "r"(a[1]), "r"(a[2]), "r"(a[3]),
          "r"(b[0]), "r"(b[1]));
}
__device__ __forceinline__ void mma16816h(float* c, const uint32_t* a,
                                          const uint32_t* b)
{
    asm volatile(
        "mma.sync.aligned.m16n8k16.row.col.f32.f16.f16.f32 "
        "{%0,%1,%2,%3}, {%4,%5,%6,%7}, {%8,%9}, {%0,%1,%2,%3};"
        : "+f"(c[0]), "+f"(c[1]), "+f"(c[2]), "+f"(c[3])
        : "r"(a[0]), "r"(a[1]), "r"(a[2]), "r"(a[3]),
          "r"(b[0]), "r"(b[1]));
}
__device__ __forceinline__ void ldsm_x4(uint32_t& r0, uint32_t& r1,
                                        uint32_t& r2, uint32_t& r3,
                                        uint32_t addr)
{
    asm volatile("ldmatrix.sync.aligned.m8n8.x4.shared.b16 {%0,%1,%2,%3}, [%4];"
                 : "=r"(r0), "=r"(r1), "=r"(r2), "=r"(r3) : "r"(addr));
}
__device__ __forceinline__ uint32_t smem_u32(const void* p) {
    uint32_t a;
    asm("{ .reg .u64 t; cvta.to.shared.u64 t, %1; cvt.u32.u64 %0, t; }"
        : "=r"(a) : "l"(p));
    return a;
}
__device__ __forceinline__ void cp_async16(uint32_t dst, const void* src) {
    asm volatile("cp.async.cg.shared.global [%0], [%1], 16;"
                 :: "r"(dst), "l"(src) : "memory");
}
__device__ __forceinline__ void cp_commit() {
    asm volatile("cp.async.commit_group;" ::: "memory");
}
template <int N>
__device__ __forceinline__ void cp_wait() {
    asm volatile("cp.async.wait_group %0;" :: "n"(N) : "memory");
}
// bf16 hi/lo split (projection path)
__device__ __forceinline__ void split2(float x, float y,
                                       uint32_t& hi, uint32_t& lo) {
    __nv_bfloat16 hx = __float2bfloat16(x);
    __nv_bfloat16 hy = __float2bfloat16(y);
    __nv_bfloat16 lx = __float2bfloat16(x - __bfloat162float(hx));
    __nv_bfloat16 ly = __float2bfloat16(y - __bfloat162float(hy));
    hi = (uint32_t)__bfloat16_as_ushort(hx) |
         ((uint32_t)__bfloat16_as_ushort(hy) << 16);
    lo = (uint32_t)__bfloat16_as_ushort(lx) |
         ((uint32_t)__bfloat16_as_ushort(ly) << 16);
}
// fp16 hi/lo split (K/V path)
__device__ __forceinline__ void split2h(float x, float y,
                                        uint32_t& hi, uint32_t& lo) {
    __half hx = __float2half_rn(x);
    __half hy = __float2half_rn(y);
    __half lx = __float2half_rn(x - __half2float(hx));
    __half ly = __float2half_rn(y - __half2float(hy));
    hi = (uint32_t)__half_as_ushort(hx) |
         ((uint32_t)__half_as_ushort(hy) << 16);
    lo = (uint32_t)__half_as_ushort(lx) |
         ((uint32_t)__half_as_ushort(ly) << 16);
}
__device__ __forceinline__ uint32_t packh2(float x, float y) {
    __half2 t = __floats2half2_rn(x, y);    // x -> low half
    return *reinterpret_cast<uint32_t*>(&t);
}

// ---------------------------------------------------------------------------
// fp32 -> (bf16 hi, bf16 lo) split: x (single tensor)
// ---------------------------------------------------------------------------
__global__ void prep_split(const float* __restrict__ in,
                           __nv_bfloat16* __restrict__ hi,
                           __nv_bfloat16* __restrict__ lo, int n4)
{
    int i = blockIdx.x * blockDim.x + threadIdx.x;
    if (i >= n4) return;
    float4 f = ((const float4*)in)[i];
    float fv[4] = {f.x, f.y, f.z, f.w};
    __nv_bfloat16 h[4], l[4];
#pragma unroll
    for (int j = 0; j < 4; ++j) {
        h[j] = __float2bfloat16(fv[j]);
        l[j] = __float2bfloat16(fv[j] - __bfloat162float(h[j]));
    }
    ((uint2*)hi)[i] = *(uint2*)h;
    ((uint2*)lo)[i] = *(uint2*)l;
}

// All 4 weight matrices in one launch: grid (W_ELEM/4/256, 4)
__global__ void prep_split_w4(
    const float* __restrict__ wq, const float* __restrict__ wk,
    const float* __restrict__ wv, const float* __restrict__ wo,
    __nv_bfloat16* __restrict__ qh, __nv_bfloat16* __restrict__ ql,
    __nv_bfloat16* __restrict__ kh, __nv_bfloat16* __restrict__ kl,
    __nv_bfloat16* __restrict__ vh, __nv_bfloat16* __restrict__ vl,
    __nv_bfloat16* __restrict__ oh, __nv_bfloat16* __restrict__ ol)
{
    int i = blockIdx.x * blockDim.x + threadIdx.x;
    const float* in;
    __nv_bfloat16 *hi, *lo;
    if      (blockIdx.y == 0) { in = wq; hi = qh; lo = ql; }
    else if (blockIdx.y == 1) { in = wk; hi = kh; lo = kl; }
    else if (blockIdx.y == 2) { in = wv; hi = vh; lo = vl; }
    else                      { in = wo; hi = oh; lo = ol; }
    float4 f = ((const float4*)in)[i];
    float fv[4] = {f.x, f.y, f.z, f.w};
    __nv_bfloat16 h[4], l[4];
#pragma unroll
    for (int j = 0; j < 4; ++j) {
        h[j] = __float2bfloat16(fv[j]);
        l[j] = __float2bfloat16(fv[j] - __bfloat162float(h[j]));
    }
    ((uint2*)hi)[i] = *(uint2*)h;
    ((uint2*)lo)[i] = *(uint2*)l;
}

// ---------------------------------------------------------------------------
// HMMA GEMM (bf16 hi/lo 3-product). CTA 128x128, BK=32, 256 threads, 2 CTAs/SM.
// ldmatrix.x4 fragment loads. Epilogues:
// mode 0: fp32 C [M,1024]
// mode 1: Q -> fp16 (hi only) [b,h,s,d], scaled by 0.125
// mode 2: K -> fp16 hi/lo [b,h,s,d]
// mode 3: V -> fp16 hi/lo [b,h,d,s] (transposed)
// ---------------------------------------------------------------------------
#define BK        32
#define SROW      40
#define TILE_B    (128 * SROW * 2)
#define STAGE_B   (4 * TILE_B)
#define GEMM_SMEM (2 * STAGE_B)
#define NK_CHUNKS (D_MODEL / BK)

__global__ __launch_bounds__(256, 2)
void gemm_tc(const __nv_bfloat16* __restrict__ Ahi,
             const __nv_bfloat16* __restrict__ Alo,
             const __nv_bfloat16* __restrict__ B0h,
             const __nv_bfloat16* __restrict__ B0l,
             const __nv_bfloat16* __restrict__ B1h,
             const __nv_bfloat16* __restrict__ B1l,
             const __nv_bfloat16* __restrict__ B2h,
             const __nv_bfloat16* __restrict__ B2l,
             float* __restrict__ C,
             __half* __restrict__ C0h, __half* __restrict__ C0l,
             __half* __restrict__ C1h, __half* __restrict__ C1l,
             __half* __restrict__ C2h, __half* __restrict__ C2l,
             int fused)
{
    extern __shared__ __align__(16) char sm[];

    const int mode = fused ? ((int)blockIdx.z + 1) : 0;
    const __nv_bfloat16 *Bhi, *Blo;
    __half *Chi = nullptr, *Clo = nullptr;
    if (!fused || blockIdx.z == 0) { Bhi = B0h; Blo = B0l; Chi = C0h; Clo = C0l; }
    else if (blockIdx.z == 1)      { Bhi = B1h; Blo = B1l; Chi = C1h; Clo = C1l; }
    else                           { Bhi = B2h; Blo = B2l; Chi = C2h; Clo = C2l; }

    const int tid  = threadIdx.x;
    const int wid  = tid >> 5;
    const int lane = tid & 31;
    const int grp  = lane >> 2;
    const int qp   = lane & 3;
    const int lrow = lane & 7;
    const int mat  = lane >> 3;          // 0..3 (ldmatrix address group)

    const int warp_m = (wid & 1) * 64;
    const int warp_n = (wid >> 1) * 32;

    // ldmatrix per-lane address components (elements)
    const int a_row = warp_m + (mat & 1) * 8 + lrow;   // + mf*16
    const int a_col = (mat >> 1) * 8;                  // + kb
    const int b_row = warp_n + (mat >> 1) * 8 + lrow;  // + nfp*16
    const int b_col = (mat & 1) * 8;                   // + kb

    const int m0 = blockIdx.y * 128;
    const int n0 = blockIdx.x * 128;

    const __nv_bfloat16* srcs[4] = {
        Ahi + (size_t)m0 * D_MODEL, Alo + (size_t)m0 * D_MODEL,
        Bhi + (size_t)n0 * D_MODEL, Blo + (size_t)n0 * D_MODEL
    };

    const uint32_t smbase = smem_u32(sm);

    auto load_stage = [&](int stage, int k0) {
        uint32_t dst0 = smbase + stage * STAGE_B;
#pragma unroll
        for (int a = 0; a < 4; ++a) {
#pragma unroll
            for (int it = 0; it < 2; ++it) {
                int g   = tid + it * 256;
                int row = g >> 2;
                int q   = g & 3;
                const __nv_bfloat16* src = srcs[a] + (size_t)row * D_MODEL + k0 + q * 8;
                cp_async16(dst0 + a * TILE_B + (row * SROW + q * 8) * 2, src);
            }
        }
        cp_commit();
    };

    float acc[4][4][4];
#pragma unroll
    for (int mf = 0; mf < 4; ++mf)
#pragma unroll
        for (int nf = 0; nf < 4; ++nf)
#pragma unroll
            for (int r = 0; r < 4; ++r) acc[mf][nf][r] = 0.0f;

    load_stage(0, 0);
    load_stage(1, BK);

    for (int kc = 0; kc < NK_CHUNKS; ++kc) {
        if (kc < NK_CHUNKS - 2) cp_wait<1>();
        else                    cp_wait<0>();
        __syncthreads();

        const int st = kc & 1;
        const uint32_t ah_base = smbase + st * STAGE_B;
        const uint32_t al_base = ah_base + TILE_B;
        const uint32_t bh_base = ah_base + 2 * TILE_B;
        const uint32_t bl_base = ah_base + 3 * TILE_B;

#pragma unroll
        for (int ks = 0; ks < 2; ++ks) {
            const int kb = ks * 16;
            // B fragments: 2 x4-LDSM per precision (4 nf x 2 regs)
            uint32_t bhi[4][2], blo[4][2];
#pragma unroll
            for (int nfp = 0; nfp < 2; ++nfp) {
                uint32_t off = (uint32_t)(((b_row + nfp * 16) * SROW + b_col + kb) * 2);
                ldsm_x4(bhi[2*nfp][0], bhi[2*nfp][1],
                        bhi[2*nfp+1][0], bhi[2*nfp+1][1], bh_base + off);
                ldsm_x4(blo[2*nfp][0], blo[2*nfp][1],
                        blo[2*nfp+1][0], blo[2*nfp+1][1], bl_base + off);
            }
            // A fragments per-mf: 2 x4-LDSM, then 12 MMAs
#pragma unroll
            for (int mf = 0; mf < 4; ++mf) {
                uint32_t off = (uint32_t)(((a_row + mf * 16) * SROW + a_col + kb) * 2);
                uint32_t ah[4], al[4];
                ldsm_x4(ah[0], ah[1], ah[2], ah[3], ah_base + off);
                ldsm_x4(al[0], al[1], al[2], al[3], al_base + off);
#pragma unroll
                for (int nf = 0; nf < 4; ++nf) {
                    mma16816(acc[mf][nf], ah, bhi[nf]);
                    mma16816(acc[mf][nf], ah, blo[nf]);
                    mma16816(acc[mf][nf], al, bhi[nf]);
                }
            }
        }
        __syncthreads();
        if (kc + 2 < NK_CHUNKS) load_stage(st, (kc + 2) * BK);
    }

    // Epilogue
    const float scale = (mode == 1) ? 0.125f : 1.0f;
#pragma unroll
    for (int mf = 0; mf < 4; ++mf) {
#pragma unroll
        for (int half = 0; half < 2; ++half) {
            int m = m0 + warp_m + mf * 16 + grp + half * 8;
            int b = m >> 11, s = m & (SEQ - 1);
#pragma unroll
            for (int nf = 0; nf < 4; ++nf) {
                int n = n0 + warp_n + nf * 8 + qp * 2;
                float vx = acc[mf][nf][half * 2];
                float vy = acc[mf][nf][half * 2 + 1];
                if (mode == 0) {
                    *(float2*)&C[(size_t)m * D_MODEL + n] = make_float2(vx, vy);
                } else if (mode == 1) {
                    int h = n >> 6, d = n & 63;
                    size_t base = ((size_t)(b * NUM_HEADS + h) * SEQ + s) * D_K + d;
                    *(uint32_t*)&Chi[base] = packh2(vx * scale, vy * scale);
                } else {
                    int h = n >> 6, d = n & 63;
                    uint32_t hp, lp;
                    split2h(vx, vy, hp, lp);
                    if (mode == 2) {
                        size_t base = ((size_t)(b * NUM_HEADS + h) * SEQ + s) * D_K + d;
                        *(uint32_t*)&Chi[base] = hp;
                        *(uint32_t*)&Clo[base] = lp;
                    } else {
                        size_t base = ((size_t)(b * NUM_HEADS + h) * D_K + d) * SEQ + s;
                        Chi[base]        = __ushort_as_half((uint16_t)hp);
                        Clo[base]        = __ushort_as_half((uint16_t)lp);
                        Chi[base + SEQ]  = __ushort_as_half((uint16_t)(hp >> 16));
                        Clo[base + SEQ]  = __ushort_as_half((uint16_t)(lp >> 16));
                    }
                }
            }
        }
    }
}

// ---------------------------------------------------------------------------
// HMMA flash attention (causal, online softmax, fp16 2+2 scheme).
// 256 threads (8 warps), BM=128 (16 rows/warp), BN=64. Q plain fp16
// (pre-scaled); K hi/lo fp16; P plain fp16; V hi/lo fp16 transposed.
// S = Qh*Kh + Qh*Kl (2 MMA); O += P*Vh + P*Vl (2 MMA).
// Output written as bf16 hi/lo in merged [tok,1024] layout.
// ---------------------------------------------------------------------------
#define FROW     72                         // 64 + 8 pad (fp16)
#define FTILE    (64 * FROW)                // elems per tile
#define FSTAGE   (4 * FTILE)                // Kh,Kl,Vth,Vtl
#define FA_SMEM  (2 * FSTAGE * 2)           // bytes = 73728

__global__ __launch_bounds__(256, 2)
void flash_tc(const __half* __restrict__ q,
              const __half* __restrict__ khh,
              const __half* __restrict__ khl,
              const __half* __restrict__ vth,
              const __half* __restrict__ vtl,
              __nv_bfloat16* __restrict__ ohi,
              __nv_bfloat16* __restrict__ olo)
{
    extern __shared__ __align__(16) __half fsh[];

    const int tid  = threadIdx.x;
    const int w    = tid >> 5;               // 0..7
    const int lane = tid & 31;
    const int grp  = lane >> 2;
    const int qp   = lane & 3;

    const int bh = blockIdx.y;
    const int b  = bh >> 4;
    const int h  = bh & 15;
    const int i0 = blockIdx.x * 128;         // query tile start (128 rows)

    // Q fragments (plain fp16, pre-scaled by 0.125)
    uint32_t qhf[4][4];
    {
        const __half* qp0 = q + ((size_t)bh * SEQ + i0 + w * 16) * D_K;
#pragma unroll
        for (int kf = 0; kf < 4; ++kf) {
            int c0 = kf * 16 + qp * 2;
            qhf[kf][0] = *(const uint32_t*)&qp0[grp * D_K + c0];
            qhf[kf][1] = *(const uint32_t*)&qp0[(grp + 8) * D_K + c0];
            qhf[kf][2] = *(const uint32_t*)&qp0[grp * D_K + c0 + 8];
            qhf[kf][3] = *(const uint32_t*)&qp0[(grp + 8) * D_K + c0 + 8];
        }
    }

    const uint32_t smbase = smem_u32(fsh);

    auto load_kv = [&](int stage, int j0) {
        uint32_t dstb = smbase + stage * FSTAGE * 2;
#pragma unroll
        for (int t8 = 0; t8 < 8; ++t8) {
            int c    = tid + t8 * 256;
            int tile = c >> 9;
            int idx  = c & 511;
            int row  = idx >> 3;
            int c8   = idx & 7;
            const __half* sp;
            if (tile == 0)
                sp = khh + ((size_t)bh * SEQ + j0 + row) * D_K + c8 * 8;
            else if (tile == 1)
                sp = khl + ((size_t)bh * SEQ + j0 + row) * D_K + c8 * 8;
            else if (tile == 2)
                sp = vth + ((size_t)bh * D_K + row) * SEQ + j0 + c8 * 8;
            else
                sp = vtl + ((size_t)bh * D_K + row) * SEQ + j0 + c8 * 8;
            cp_async16(dstb + (tile * FTILE + row * FROW + c8 * 8) * 2, sp);
        }
        cp_commit();
    };

    float oacc[8][4];
#pragma unroll
    for (int nf = 0; nf < 8; ++nf)
#pragma unroll
        for (int r = 0; r < 4; ++r) oacc[nf][r] = 0.0f;
    float m0v = -1e30f, m1v = -1e30f, l0 = 0.0f, l1 = 0.0f;

    const int nt = i0 / 64 + 2;              // key tiles j0 = 0 .. i0+64
    load_kv(0, 0);

    for (int t = 0; t < nt; ++t) {
        const int st = t & 1;
        const int j0 = t * 64;
        if (t + 1 < nt) { load_kv(st ^ 1, (t + 1) * 64); cp_wait<1>(); }
        else            { cp_wait<0>(); }
        __syncthreads();

        const __half* Kh = fsh + st * FSTAGE;
        const __half* Kl = Kh + FTILE;
        const __half* Vh = Kh + 2 * FTILE;
        const __half* Vl = Kh + 3 * FTILE;

        // S = Q K^T (2-MMA: Qh*Kh + Qh*Kl)
        float sacc[8][4];
#pragma unroll
        for (int nf = 0; nf < 8; ++nf)
#pragma unroll
            for (int r = 0; r < 4; ++r) sacc[nf][r] = 0.0f;

#pragma unroll
        for (int nf = 0; nf < 8; ++nf) {
            const int rb = (nf * 8 + grp) * FROW;
#pragma unroll
            for (int kf = 0; kf < 4; ++kf) {
                const int cc = kf * 16 + qp * 2;
                uint32_t bkh[2] = { *(const uint32_t*)&Kh[rb + cc],
                                    *(const uint32_t*)&Kh[rb + cc + 8] };
                uint32_t bkl[2] = { *(const uint32_t*)&Kl[rb + cc],
                                    *(const uint32_t*)&Kl[rb + cc + 8] };
                mma16816h(sacc[nf], qhf[kf], bkh);
                mma16816h(sacc[nf], qhf[kf], bkl);
            }
        }

        // causal mask (any tile overlapping this warp's rows; warp-uniform test)
        if (j0 + 64 > i0 + w * 16) {
            const int grow0 = i0 + w * 16 + grp;
#pragma unroll
            for (int nf = 0; nf < 8; ++nf) {
                int gc = j0 + nf * 8 + qp * 2;
                if (gc     > grow0)     sacc[nf][0] = -1e30f;
                if (gc + 1 > grow0)     sacc[nf][1] = -1e30f;
                if (gc     > grow0 + 8) sacc[nf][2] = -1e30f;
                if (gc + 1 > grow0 + 8) sacc[nf][3] = -1e30f;
            }
        }

        // row max (own 16 + quad shfl)
        float mx0 = -1e30f, mx1 = -1e30f;
#pragma unroll
        for (int nf = 0; nf < 8; ++nf) {
            mx0 = fmaxf(mx0, fmaxf(sacc[nf][0], sacc[nf][1]));
            mx1 = fmaxf(mx1, fmaxf(sacc[nf][2], sacc[nf][3]));
        }
        mx0 = fmaxf(mx0, __shfl_xor_sync(0xffffffffu, mx0, 1));
        mx0 = fmaxf(mx0, __shfl_xor_sync(0xffffffffu, mx0, 2));
        mx1 = fmaxf(mx1, __shfl_xor_sync(0xffffffffu, mx1, 1));
        mx1 = fmaxf(mx1, __shfl_xor_sync(0xffffffffu, mx1, 2));

        float mn0 = fmaxf(m0v, mx0), mn1 = fmaxf(m1v, mx1);
        float a0 = __expf(m0v - mn0), a1 = __expf(m1v - mn1);
        m0v = mn0; m1v = mn1;

        // P = exp(S - m), plain fp16, packed as A-fragments
        float s0 = 0.0f, s1 = 0.0f;
        uint32_t ph01[8], ph23[8];
#pragma unroll
        for (int nf = 0; nf < 8; ++nf) {
            float p0 = __expf(sacc[nf][0] - mn0);
            float p1 = __expf(sacc[nf][1] - mn0);
            float p2 = __expf(sacc[nf][2] - mn1);
            float p3 = __expf(sacc[nf][3] - mn1);
            s0 += p0 + p1; s1 += p2 + p3;
            ph01[nf] = packh2(p0, p1);
            ph23[nf] = packh2(p2, p3);
        }
        s0 += __shfl_xor_sync(0xffffffffu, s0, 1);
        s0 += __shfl_xor_sync(0xffffffffu, s0, 2);
        s1 += __shfl_xor_sync(0xffffffffu, s1, 1);
        s1 += __shfl_xor_sync(0xffffffffu, s1, 2);
        l0 = l0 * a0 + s0;
        l1 = l1 * a1 + s1;

#pragma unroll
        for (int nf = 0; nf < 8; ++nf) {
            oacc[nf][0] *= a0; oacc[nf][1] *= a0;
            oacc[nf][2] *= a1; oacc[nf][3] *= a1;
        }

        // O += P V   (2-MMA: P*Vh + P*Vl; Vt tiles [d][j], NT pattern)
#pragma unroll
        for (int nfd = 0; nfd < 8; ++nfd) {
            const int rb = (nfd * 8 + grp) * FROW;
#pragma unroll
            for (int kf = 0; kf < 4; ++kf) {
                const int cc = kf * 16 + qp * 2;
                uint32_t bvh[2] = { *(const uint32_t*)&Vh[rb + cc],
                                    *(const uint32_t*)&Vh[rb + cc + 8] };
                uint32_t bvl[2] = { *(const uint32_t*)&Vl[rb + cc],
                                    *(const uint32_t*)&Vl[rb + cc + 8] };
                uint32_t ap[4] = { ph01[2 * kf], ph23[2 * kf],
                                   ph01[2 * kf + 1], ph23[2 * kf + 1] };
                mma16816h(oacc[nfd], ap, bvh);
                mma16816h(oacc[nfd], ap, bvl);
            }
        }
        __syncthreads();
    }

    // epilogue: normalize, split to bf16 hi/lo, write merged [tok, h*64+d]
    const float il0 = 1.0f / l0, il1 = 1.0f / l1;
    const size_t tok0 = (size_t)b * SEQ + i0 + w * 16 + grp;
#pragma unroll
    for (int nf = 0; nf < 8; ++nf) {
        int col = h * D_K + nf * 8 + qp * 2;
        uint32_t hp, lp;
        split2(oacc[nf][0] * il0, oacc[nf][1] * il0, hp, lp);
        *(uint32_t*)&ohi[tok0 * D_MODEL + col] = hp;
        *(uint32_t*)&olo[tok0 * D_MODEL + col] = lp;
        split2(oacc[nf][2] * il1, oacc[nf][3] * il1, hp, lp);
        *(uint32_t*)&ohi[(tok0 + 8) * D_MODEL + col] = hp;
        *(uint32_t*)&olo[(tok0 + 8) * D_MODEL + col] = lp;
    }
}

// ---------------------------------------------------------------------------
// Launch
// ---------------------------------------------------------------------------
extern "C" void kernel_launch(void* const* d_in, const int* in_sizes, int n_in,
                              void* d_out, int out_size)
{
    const float* x  = (const float*)d_in[0];
    const float* wq = (const float*)d_in[1];
    const float* wk = (const float*)d_in[2];
    const float* wv = (const float*)d_in[3];
    const float* wo = (const float*)d_in[4];
    float* out = (float*)d_out;

    __nv_bfloat16 *xhi, *xlo, *wqhi, *wqlo, *wkhi, *wklo, *wvhi, *wvlo,
                  *wohi, *wolo, *ohi, *olo;
    __half *qh, *kh, *kl, *vth, *vtl;
    cudaGetSymbolAddress((void**)&xhi, g_xhi);
    cudaGetSymbolAddress((void**)&xlo, g_xlo);
    cudaGetSymbolAddress((void**)&wqhi, g_wqhi);
    cudaGetSymbolAddress((void**)&wqlo, g_wqlo);
    cudaGetSymbolAddress((void**)&wkhi, g_wkhi);
    cudaGetSymbolAddress((void**)&wklo, g_wklo);
    cudaGetSymbolAddress((void**)&wvhi, g_wvhi);
    cudaGetSymbolAddress((void**)&wvlo, g_wvlo);
    cudaGetSymbolAddress((void**)&wohi, g_wohi);
    cudaGetSymbolAddress((void**)&wolo, g_wolo);
    cudaGetSymbolAddress((void**)&qh, g_qh);
    cudaGetSymbolAddress((void**)&kh, g_kh);
    cudaGetSymbolAddress((void**)&kl, g_kl);
    cudaGetSymbolAddress((void**)&vth, g_vth);
    cudaGetSymbolAddress((void**)&vtl, g_vtl);
    cudaGetSymbolAddress((void**)&ohi, g_ohi);
    cudaGetSymbolAddress((void**)&olo, g_olo);

    cudaFuncSetAttribute(gemm_tc, cudaFuncAttributeMaxDynamicSharedMemorySize,
                         GEMM_SMEM);
    cudaFuncSetAttribute(flash_tc, cudaFuncAttributeMaxDynamicSharedMemorySize,
                         FA_SMEM);

    prep_split<<<NELEM / 4 / 256, 256>>>(x, xhi, xlo, NELEM / 4);
    dim3 wGrid(W_ELEM / 4 / 256, 4);                 // (1024, 4)
    prep_split_w4<<<wGrid, 256>>>(wq, wk, wv, wo,
                                  wqhi, wqlo, wkhi, wklo,
                                  wvhi, wvlo, wohi, wolo);

    // Fused Q/K/V projections: grid.z selects weight + epilogue
    dim3 qkvGrid(D_MODEL / 128, M_TOKENS / 128, 3);  // (8, 64, 3)
    gemm_tc<<<qkvGrid, 256, GEMM_SMEM>>>(
        xhi, xlo,
        wqhi, wqlo, wkhi, wklo, wvhi, wvlo,
        nullptr,
        qh, nullptr, kh, kl, vth, vtl, 1);

    dim3 attnGrid(SEQ / 128, BATCH * NUM_HEADS);     // (16, 64)
    flash_tc<<<attnGrid, 256, FA_SMEM>>>(qh, kh, kl, vth, vtl, ohi, olo);

    // Output projection (mode 0)
    dim3 oGrid(D_MODEL / 128, M_TOKENS / 128, 1);    // (8, 64)
    gemm_tc<<<oGrid, 256, GEMM_SMEM>>>(
        ohi, olo,
        wohi, wolo, wohi, wolo, wohi, wolo,
        out,
        nullptr, nullptr, nullptr, nullptr, nullptr, nullptr, 0);
}

// round 15
// speedup vs baseline: 1.4828x; 1.3210x over previous
#include <cuda_runtime.h>
#include <cuda_bf16.h>
#include <cuda_fp16.h>
#include <cstdint>

#define D_MODEL   1024
#define NUM_HEADS 16
#define D_K       64
#define BATCH     4
#define SEQ       2048
#define M_TOKENS  (BATCH * SEQ)          // 8192
#define NELEM     (M_TOKENS * D_MODEL)   // 8388608
#define W_ELEM    (D_MODEL * D_MODEL)    // 1048576

// ---------------------------------------------------------------------------
// Scratch (allocation-free)
// ---------------------------------------------------------------------------
__device__ __half g_xh[NELEM];                         // x plain fp16
__device__ __half g_wqh[W_ELEM], g_wql[W_ELEM];        // weights fp16 hi/lo
__device__ __half g_wkh[W_ELEM], g_wkl[W_ELEM];
__device__ __half g_wvh[W_ELEM], g_wvl[W_ELEM];
__device__ __half g_woh[W_ELEM], g_wol[W_ELEM];
__device__ __half g_qh[NELEM];                         // Q fp16 [b,h,s,d], pre-scaled
__device__ __half g_kh[NELEM],  g_kl[NELEM];           // K fp16 hi/lo [b,h,s,d]
__device__ __half g_vth[NELEM], g_vtl[NELEM];          // V fp16 hi/lo [b,h,d,s]
__device__ __half g_oh[NELEM];                         // attn out plain fp16 [tok,1024]

// ---------------------------------------------------------------------------
// helpers
// ---------------------------------------------------------------------------
__device__ __forceinline__ void mma16816h(float* c, const uint32_t* a,
                                          const uint32_t* b)
{
    asm volatile(
        "mma.sync.aligned.m16n8k16.row.col.f32.f16.f16.f32 "
        "{%0,%1,%2,%3}, {%4,%5,%6,%7}, {%8,%9}, {%0,%1,%2,%3};"
        : "+f"(c[0]), "+f"(c[1]), "+f"(c[2]), "+f"(c[3])
        : "r"(a[0]), "r"(a[1]), "r"(a[2]), "r"(a[3]),
          "r"(b[0]), "r"(b[1]));
}
__device__ __forceinline__ void ldsm_x4(uint32_t& r0, uint32_t& r1,
                                        uint32_t& r2, uint32_t& r3,
                                        uint32_t addr)
{
    asm volatile("ldmatrix.sync.aligned.m8n8.x4.shared.b16 {%0,%1,%2,%3}, [%4];"
                 : "=r"(r0), "=r"(r1), "=r"(r2), "=r"(r3) : "r"(addr));
}
__device__ __forceinline__ uint32_t smem_u32(const void* p) {
    uint32_t a;
    asm("{ .reg .u64 t; cvta.to.shared.u64 t, %1; cvt.u32.u64 %0, t; }"
        : "=r"(a) : "l"(p));
    return a;
}
__device__ __forceinline__ void cp_async16(uint32_t dst, const void* src) {
    asm volatile("cp.async.cg.shared.global [%0], [%1], 16;"
                 :: "r"(dst), "l"(src) : "memory");
}
__device__ __forceinline__ void cp_commit() {
    asm volatile("cp.async.commit_group;" ::: "memory");
}
template <int N>
__device__ __forceinline__ void cp_wait() {
    asm volatile("cp.async.wait_group %0;" :: "n"(N) : "memory");
}
// fp16 hi/lo split
__device__ __forceinline__ void split2h(float x, float y,
                                        uint32_t& hi, uint32_t& lo) {
    __half hx = __float2half_rn(x);
    __half hy = __float2half_rn(y);
    __half lx = __float2half_rn(x - __half2float(hx));
    __half ly = __float2half_rn(y - __half2float(hy));
    hi = (uint32_t)__half_as_ushort(hx) |
         ((uint32_t)__half_as_ushort(hy) << 16);
    lo = (uint32_t)__half_as_ushort(lx) |
         ((uint32_t)__half_as_ushort(ly) << 16);
}
__device__ __forceinline__ uint32_t packh2(float x, float y) {
    __half2 t = __floats2half2_rn(x, y);    // x -> low half
    return *reinterpret_cast<uint32_t*>(&t);
}

// ---------------------------------------------------------------------------
// fp32 -> plain fp16 (x)
// ---------------------------------------------------------------------------
__global__ void prep_half(const float* __restrict__ in,
                          __half* __restrict__ out, int n4)
{
    int i = blockIdx.x * blockDim.x + threadIdx.x;
    if (i >= n4) return;
    float4 f = ((const float4*)in)[i];
    uint2 o;
    o.x = packh2(f.x, f.y);
    o.y = packh2(f.z, f.w);
    ((uint2*)out)[i] = o;
}

// All 4 weight matrices -> fp16 hi/lo, one launch: grid (W_ELEM/4/256, 4)
__global__ void prep_split_w4(
    const float* __restrict__ wq, const float* __restrict__ wk,
    const float* __restrict__ wv, const float* __restrict__ wo,
    __half* __restrict__ qh, __half* __restrict__ ql,
    __half* __restrict__ kh, __half* __restrict__ kl,
    __half* __restrict__ vh, __half* __restrict__ vl,
    __half* __restrict__ oh, __half* __restrict__ ol)
{
    int i = blockIdx.x * blockDim.x + threadIdx.x;
    const float* in;
    __half *hi, *lo;
    if      (blockIdx.y == 0) { in = wq; hi = qh; lo = ql; }
    else if (blockIdx.y == 1) { in = wk; hi = kh; lo = kl; }
    else if (blockIdx.y == 2) { in = wv; hi = vh; lo = vl; }
    else                      { in = wo; hi = oh; lo = ol; }
    float4 f = ((const float4*)in)[i];
    uint2 h, l;
    uint32_t h0, l0, h1, l1;
    split2h(f.x, f.y, h0, l0);
    split2h(f.z, f.w, h1, l1);
    h.x = h0; h.y = h1; l.x = l0; l.y = l1;
    ((uint2*)hi)[i] = h;
    ((uint2*)lo)[i] = l;
}

// ---------------------------------------------------------------------------
// HMMA GEMM, fp16 2-product: A plain fp16, B fp16 hi/lo.
// C = A*Bh + A*Bl. CTA 128x128, BK=32, 256 threads, 2 CTAs/SM, ldmatrix.
// fused=1: grid.z in {0,1,2} selects Q/K/V weight + epilogue mode z+1.
// fused=0: output projection, fp32 epilogue (mode 0).
// mode 1: Q -> plain fp16 [b,h,s,d], scaled by 0.125
// mode 2: K -> fp16 hi/lo [b,h,s,d]
// mode 3: V -> fp16 hi/lo [b,h,d,s] (transposed)
// ---------------------------------------------------------------------------
#define BK        32
#define SROW      40
#define TILE_B    (128 * SROW * 2)           // 10240 bytes
#define STAGE_B   (3 * TILE_B)               // A, Bh, Bl = 30720
#define GEMM_SMEM (2 * STAGE_B)              // 61440
#define NK_CHUNKS (D_MODEL / BK)

__global__ __launch_bounds__(256, 2)
void gemm_tc(const __half* __restrict__ A,
             const __half* __restrict__ B0h, const __half* __restrict__ B0l,
             const __half* __restrict__ B1h, const __half* __restrict__ B1l,
             const __half* __restrict__ B2h, const __half* __restrict__ B2l,
             float* __restrict__ C,
             __half* __restrict__ C0, __half* __restrict__ C1h,
             __half* __restrict__ C1l, __half* __restrict__ C2h,
             __half* __restrict__ C2l,
             int fused)
{
    extern __shared__ __align__(16) char sm[];

    const int mode = fused ? ((int)blockIdx.z + 1) : 0;
    const __half *Bhi, *Blo;
    __half *Chi = nullptr, *Clo = nullptr;
    if (!fused || blockIdx.z == 0) { Bhi = B0h; Blo = B0l; Chi = C0; Clo = nullptr; }
    else if (blockIdx.z == 1)      { Bhi = B1h; Blo = B1l; Chi = C1h; Clo = C1l; }
    else                           { Bhi = B2h; Blo = B2l; Chi = C2h; Clo = C2l; }

    const int tid  = threadIdx.x;
    const int wid  = tid >> 5;
    const int lane = tid & 31;
    const int grp  = lane >> 2;
    const int qp   = lane & 3;
    const int lrow = lane & 7;
    const int mat  = lane >> 3;

    const int warp_m = (wid & 1) * 64;
    const int warp_n = (wid >> 1) * 32;

    const int a_row = warp_m + (mat & 1) * 8 + lrow;   // + mf*16
    const int a_col = (mat >> 1) * 8;                  // + kb
    const int b_row = warp_n + (mat >> 1) * 8 + lrow;  // + nfp*16
    const int b_col = (mat & 1) * 8;                   // + kb

    const int m0 = blockIdx.y * 128;
    const int n0 = blockIdx.x * 128;

    const __half* srcs[3] = {
        A   + (size_t)m0 * D_MODEL,
        Bhi + (size_t)n0 * D_MODEL,
        Blo + (size_t)n0 * D_MODEL
    };

    const uint32_t smbase = smem_u32(sm);

    auto load_stage = [&](int stage, int k0) {
        uint32_t dst0 = smbase + stage * STAGE_B;
#pragma unroll
        for (int a = 0; a < 3; ++a) {
#pragma unroll
            for (int it = 0; it < 2; ++it) {
                int g   = tid + it * 256;
                int row = g >> 2;
                int q   = g & 3;
                const __half* src = srcs[a] + (size_t)row * D_MODEL + k0 + q * 8;
                cp_async16(dst0 + a * TILE_B + (row * SROW + q * 8) * 2, src);
            }
        }
        cp_commit();
    };

    float acc[4][4][4];
#pragma unroll
    for (int mf = 0; mf < 4; ++mf)
#pragma unroll
        for (int nf = 0; nf < 4; ++nf)
#pragma unroll
            for (int r = 0; r < 4; ++r) acc[mf][nf][r] = 0.0f;

    load_stage(0, 0);
    load_stage(1, BK);

    for (int kc = 0; kc < NK_CHUNKS; ++kc) {
        if (kc < NK_CHUNKS - 2) cp_wait<1>();
        else                    cp_wait<0>();
        __syncthreads();

        const int st = kc & 1;
        const uint32_t a_base  = smbase + st * STAGE_B;
        const uint32_t bh_base = a_base + TILE_B;
        const uint32_t bl_base = a_base + 2 * TILE_B;

#pragma unroll
        for (int ks = 0; ks < 2; ++ks) {
            const int kb = ks * 16;
            uint32_t bhi[4][2], blo[4][2];
#pragma unroll
            for (int nfp = 0; nfp < 2; ++nfp) {
                uint32_t off = (uint32_t)(((b_row + nfp * 16) * SROW + b_col + kb) * 2);
                ldsm_x4(bhi[2*nfp][0], bhi[2*nfp][1],
                        bhi[2*nfp+1][0], bhi[2*nfp+1][1], bh_base + off);
                ldsm_x4(blo[2*nfp][0], blo[2*nfp][1],
                        blo[2*nfp+1][0], blo[2*nfp+1][1], bl_base + off);
            }
#pragma unroll
            for (int mf = 0; mf < 4; ++mf) {
                uint32_t off = (uint32_t)(((a_row + mf * 16) * SROW + a_col + kb) * 2);
                uint32_t ah[4];
                ldsm_x4(ah[0], ah[1], ah[2], ah[3], a_base + off);
#pragma unroll
                for (int nf = 0; nf < 4; ++nf) {
                    mma16816h(acc[mf][nf], ah, bhi[nf]);
                    mma16816h(acc[mf][nf], ah, blo[nf]);
                }
            }
        }
        __syncthreads();
        if (kc + 2 < NK_CHUNKS) load_stage(st, (kc + 2) * BK);
    }

    // Epilogue
    const float scale = (mode == 1) ? 0.125f : 1.0f;
#pragma unroll
    for (int mf = 0; mf < 4; ++mf) {
#pragma unroll
        for (int half = 0; half < 2; ++half) {
            int m = m0 + warp_m + mf * 16 + grp + half * 8;
            int b = m >> 11, s = m & (SEQ - 1);
#pragma unroll
            for (int nf = 0; nf < 4; ++nf) {
                int n = n0 + warp_n + nf * 8 + qp * 2;
                float vx = acc[mf][nf][half * 2];
                float vy = acc[mf][nf][half * 2 + 1];
                if (mode == 0) {
                    *(float2*)&C[(size_t)m * D_MODEL + n] = make_float2(vx, vy);
                } else if (mode == 1) {
                    int h = n >> 6, d = n & 63;
                    size_t base = ((size_t)(b * NUM_HEADS + h) * SEQ + s) * D_K + d;
                    *(uint32_t*)&Chi[base] = packh2(vx * scale, vy * scale);
                } else {
                    int h = n >> 6, d = n & 63;
                    uint32_t hp, lp;
                    split2h(vx, vy, hp, lp);
                    if (mode == 2) {
                        size_t base = ((size_t)(b * NUM_HEADS + h) * SEQ + s) * D_K + d;
                        *(uint32_t*)&Chi[base] = hp;
                        *(uint32_t*)&Clo[base] = lp;
                    } else {
                        size_t base = ((size_t)(b * NUM_HEADS + h) * D_K + d) * SEQ + s;
                        Chi[base]        = __ushort_as_half((uint16_t)hp);
                        Clo[base]        = __ushort_as_half((uint16_t)lp);
                        Chi[base + SEQ]  = __ushort_as_half((uint16_t)(hp >> 16));
                        Clo[base + SEQ]  = __ushort_as_half((uint16_t)(lp >> 16));
                    }
                }
            }
        }
    }
}

// ---------------------------------------------------------------------------
// HMMA flash attention (causal, online softmax, fp16 2+2 scheme).
// 256 threads (8 warps), BM=128, BN=64. Q plain fp16 (pre-scaled);
// K hi/lo fp16; P plain fp16; V hi/lo fp16 transposed.
// B-fragments loaded via ldmatrix.x4 (per-kf, two 4-nf half-batches).
// Output written as plain fp16 in merged [tok,1024] layout.
// ---------------------------------------------------------------------------
#define FROW     72                         // 64 + 8 pad (fp16)
#define FTILE    (64 * FROW)                // elems per tile
#define FSTAGE   (4 * FTILE)                // Kh,Kl,Vth,Vtl
#define FA_SMEM  (2 * FSTAGE * 2)           // bytes = 73728

__global__ __launch_bounds__(256, 2)
void flash_tc(const __half* __restrict__ q,
              const __half* __restrict__ khh,
              const __half* __restrict__ khl,
              const __half* __restrict__ vth,
              const __half* __restrict__ vtl,
              __half* __restrict__ oh)
{
    extern __shared__ __align__(16) __half fsh[];

    const int tid  = threadIdx.x;
    const int w    = tid >> 5;               // 0..7
    const int lane = tid & 31;
    const int grp  = lane >> 2;
    const int qp   = lane & 3;
    const int lrow = lane & 7;
    const int mat  = lane >> 3;

    const int bh = blockIdx.y;
    const int b  = bh >> 4;
    const int h  = bh & 15;
    const int i0 = blockIdx.x * 128;         // query tile start (128 rows)

    // ldmatrix per-lane address components for B-frag loads (elements)
    const int b_row = (mat >> 1) * 8 + lrow;   // + nfp*16
    const int b_col = (mat & 1) * 8;           // + kf*16

    // Q fragments (plain fp16, pre-scaled by 0.125)
    uint32_t qhf[4][4];
    {
        const __half* qp0 = q + ((size_t)bh * SEQ + i0 + w * 16) * D_K;
#pragma unroll
        for (int kf = 0; kf < 4; ++kf) {
            int c0 = kf * 16 + qp * 2;
            qhf[kf][0] = *(const uint32_t*)&qp0[grp * D_K + c0];
            qhf[kf][1] = *(const uint32_t*)&qp0[(grp + 8) * D_K + c0];
            qhf[kf][2] = *(const uint32_t*)&qp0[grp * D_K + c0 + 8];
            qhf[kf][3] = *(const uint32_t*)&qp0[(grp + 8) * D_K + c0 + 8];
        }
    }

    const uint32_t smbase = smem_u32(fsh);

    auto load_kv = [&](int stage, int j0) {
        uint32_t dstb = smbase + stage * FSTAGE * 2;
#pragma unroll
        for (int t8 = 0; t8 < 8; ++t8) {
            int c    = tid + t8 * 256;
            int tile = c >> 9;
            int idx  = c & 511;
            int row  = idx >> 3;
            int c8   = idx & 7;
            const __half* sp;
            if (tile == 0)
                sp = khh + ((size_t)bh * SEQ + j0 + row) * D_K + c8 * 8;
            else if (tile == 1)
                sp = khl + ((size_t)bh * SEQ + j0 + row) * D_K + c8 * 8;
            else if (tile == 2)
                sp = vth + ((size_t)bh * D_K + row) * SEQ + j0 + c8 * 8;
            else
                sp = vtl + ((size_t)bh * D_K + row) * SEQ + j0 + c8 * 8;
            cp_async16(dstb + (tile * FTILE + row * FROW + c8 * 8) * 2, sp);
        }
        cp_commit();
    };

    float oacc[8][4];
#pragma unroll
    for (int nf = 0; nf < 8; ++nf)
#pragma unroll
        for (int r = 0; r < 4; ++r) oacc[nf][r] = 0.0f;
    float m0v = -1e30f, m1v = -1e30f, l0 = 0.0f, l1 = 0.0f;

    const int nt = i0 / 64 + 2;              // key tiles j0 = 0 .. i0+64
    load_kv(0, 0);

    for (int t = 0; t < nt; ++t) {
        const int st = t & 1;
        const int j0 = t * 64;
        if (t + 1 < nt) { load_kv(st ^ 1, (t + 1) * 64); cp_wait<1>(); }
        else            { cp_wait<0>(); }
        __syncthreads();

        const uint32_t kh_base = smbase + st * FSTAGE * 2;
        const uint32_t kl_base = kh_base + FTILE * 2;
        const uint32_t vh_base = kh_base + 2 * FTILE * 2;
        const uint32_t vl_base = kh_base + 3 * FTILE * 2;

        // S = Q K^T (2-MMA: Q*Kh + Q*Kl), B-frags via ldmatrix per kf
        float sacc[8][4];
#pragma unroll
        for (int nf = 0; nf < 8; ++nf)
#pragma unroll
            for (int r = 0; r < 4; ++r) sacc[nf][r] = 0.0f;

#pragma unroll
        for (int kf = 0; kf < 4; ++kf) {
            const int cc = kf * 16;
#pragma unroll
            for (int half2x = 0; half2x < 2; ++half2x) {   // nfp pairs {0,1},{2,3}
                uint32_t bkh[4][2], bkl[4][2];
#pragma unroll
                for (int p = 0; p < 2; ++p) {
                    int nfp = half2x * 2 + p;
                    uint32_t off = (uint32_t)(((nfp * 16 + b_row) * FROW + b_col + cc) * 2);
                    ldsm_x4(bkh[2*p][0], bkh[2*p][1],
                            bkh[2*p+1][0], bkh[2*p+1][1], kh_base + off);
                    ldsm_x4(bkl[2*p][0], bkl[2*p][1],
                            bkl[2*p+1][0], bkl[2*p+1][1], kl_base + off);
                }
#pragma unroll
                for (int j = 0; j < 4; ++j) {
                    int nf = half2x * 4 + j;
                    mma16816h(sacc[nf], qhf[kf], bkh[j]);
                    mma16816h(sacc[nf], qhf[kf], bkl[j]);
                }
            }
        }

        // causal mask (any tile overlapping this warp's rows; warp-uniform test)
        if (j0 + 64 > i0 + w * 16) {
            const int grow0 = i0 + w * 16 + grp;
#pragma unroll
            for (int nf = 0; nf < 8; ++nf) {
                int gc = j0 + nf * 8 + qp * 2;
                if (gc     > grow0)     sacc[nf][0] = -1e30f;
                if (gc + 1 > grow0)     sacc[nf][1] = -1e30f;
                if (gc     > grow0 + 8) sacc[nf][2] = -1e30f;
                if (gc + 1 > grow0 + 8) sacc[nf][3] = -1e30f;
            }
        }

        // row max (own 16 + quad shfl)
        float mx0 = -1e30f, mx1 = -1e30f;
#pragma unroll
        for (int nf = 0; nf < 8; ++nf) {
            mx0 = fmaxf(mx0, fmaxf(sacc[nf][0], sacc[nf][1]));
            mx1 = fmaxf(mx1, fmaxf(sacc[nf][2], sacc[nf][3]));
        }
        mx0 = fmaxf(mx0, __shfl_xor_sync(0xffffffffu, mx0, 1));
        mx0 = fmaxf(mx0, __shfl_xor_sync(0xffffffffu, mx0, 2));
        mx1 = fmaxf(mx1, __shfl_xor_sync(0xffffffffu, mx1, 1));
        mx1 = fmaxf(mx1, __shfl_xor_sync(0xffffffffu, mx1, 2));

        float mn0 = fmaxf(m0v, mx0), mn1 = fmaxf(m1v, mx1);
        float a0 = __expf(m0v - mn0), a1 = __expf(m1v - mn1);
        m0v = mn0; m1v = mn1;

        // P = exp(S - m), plain fp16, packed as A-fragments
        float s0 = 0.0f, s1 = 0.0f;
        uint32_t ph01[8], ph23[8];
#pragma unroll
        for (int nf = 0; nf < 8; ++nf) {
            float p0 = __expf(sacc[nf][0] - mn0);
            float p1 = __expf(sacc[nf][1] - mn0);
            float p2 = __expf(sacc[nf][2] - mn1);
            float p3 = __expf(sacc[nf][3] - mn1);
            s0 += p0 + p1; s1 += p2 + p3;
            ph01[nf] = packh2(p0, p1);
            ph23[nf] = packh2(p2, p3);
        }
        s0 += __shfl_xor_sync(0xffffffffu, s0, 1);
        s0 += __shfl_xor_sync(0xffffffffu, s0, 2);
        s1 += __shfl_xor_sync(0xffffffffu, s1, 1);
        s1 += __shfl_xor_sync(0xffffffffu, s1, 2);
        l0 = l0 * a0 + s0;
        l1 = l1 * a1 + s1;

#pragma unroll
        for (int nf = 0; nf < 8; ++nf) {
            oacc[nf][0] *= a0; oacc[nf][1] *= a0;
            oacc[nf][2] *= a1; oacc[nf][3] *= a1;
        }

        // O += P V (2-MMA: P*Vh + P*Vl), V-frags via ldmatrix per kf
#pragma unroll
        for (int kf = 0; kf < 4; ++kf) {
            const int cc = kf * 16;
            uint32_t ap[4] = { ph01[2 * kf], ph23[2 * kf],
                               ph01[2 * kf + 1], ph23[2 * kf + 1] };
#pragma unroll
            for (int half2x = 0; half2x < 2; ++half2x) {
                uint32_t bvh[4][2], bvl[4][2];
#pragma unroll
                for (int p = 0; p < 2; ++p) {
                    int nfp = half2x * 2 + p;
                    uint32_t off = (uint32_t)(((nfp * 16 + b_row) * FROW + b_col + cc) * 2);
                    ldsm_x4(bvh[2*p][0], bvh[2*p][1],
                            bvh[2*p+1][0], bvh[2*p+1][1], vh_base + off);
                    ldsm_x4(bvl[2*p][0], bvl[2*p][1],
                            bvl[2*p+1][0], bvl[2*p+1][1], vl_base + off);
                }
#pragma unroll
                for (int j = 0; j < 4; ++j) {
                    int nfd = half2x * 4 + j;
                    mma16816h(oacc[nfd], ap, bvh[j]);
                    mma16816h(oacc[nfd], ap, bvl[j]);
                }
            }
        }
        __syncthreads();
    }

    // epilogue: normalize, write plain fp16, merged [tok, h*64+d]
    const float il0 = 1.0f / l0, il1 = 1.0f / l1;
    const size_t tok0 = (size_t)b * SEQ + i0 + w * 16 + grp;
#pragma unroll
    for (int nf = 0; nf < 8; ++nf) {
        int col = h * D_K + nf * 8 + qp * 2;
        *(uint32_t*)&oh[tok0 * D_MODEL + col] =
            packh2(oacc[nf][0] * il0, oacc[nf][1] * il0);
        *(uint32_t*)&oh[(tok0 + 8) * D_MODEL + col] =
            packh2(oacc[nf][2] * il1, oacc[nf][3] * il1);
    }
}

// ---------------------------------------------------------------------------
// Launch
// ---------------------------------------------------------------------------
extern "C" void kernel_launch(void* const* d_in, const int* in_sizes, int n_in,
                              void* d_out, int out_size)
{
    const float* x  = (const float*)d_in[0];
    const float* wq = (const float*)d_in[1];
    const float* wk = (const float*)d_in[2];
    const float* wv = (const float*)d_in[3];
    const float* wo = (const float*)d_in[4];
    float* out = (float*)d_out;

    __half *xh, *wqh, *wql, *wkh, *wkl, *wvh, *wvl, *woh, *wol,
           *qh, *kh, *kl, *vth, *vtl, *oh;
    cudaGetSymbolAddress((void**)&xh, g_xh);
    cudaGetSymbolAddress((void**)&wqh, g_wqh);
    cudaGetSymbolAddress((void**)&wql, g_wql);
    cudaGetSymbolAddress((void**)&wkh, g_wkh);
    cudaGetSymbolAddress((void**)&wkl, g_wkl);
    cudaGetSymbolAddress((void**)&wvh, g_wvh);
    cudaGetSymbolAddress((void**)&wvl, g_wvl);
    cudaGetSymbolAddress((void**)&woh, g_woh);
    cudaGetSymbolAddress((void**)&wol, g_wol);
    cudaGetSymbolAddress((void**)&qh, g_qh);
    cudaGetSymbolAddress((void**)&kh, g_kh);
    cudaGetSymbolAddress((void**)&kl, g_kl);
    cudaGetSymbolAddress((void**)&vth, g_vth);
    cudaGetSymbolAddress((void**)&vtl, g_vtl);
    cudaGetSymbolAddress((void**)&oh, g_oh);

    cudaFuncSetAttribute(gemm_tc, cudaFuncAttributeMaxDynamicSharedMemorySize,
                         GEMM_SMEM);
    cudaFuncSetAttribute(flash_tc, cudaFuncAttributeMaxDynamicSharedMemorySize,
                         FA_SMEM);

    prep_half<<<NELEM / 4 / 256, 256>>>(x, xh, NELEM / 4);
    dim3 wGrid(W_ELEM / 4 / 256, 4);                 // (1024, 4)
    prep_split_w4<<<wGrid, 256>>>(wq, wk, wv, wo,
                                  wqh, wql, wkh, wkl,
                                  wvh, wvl, woh, wol);

    // Fused Q/K/V projections: grid.z selects weight + epilogue
    dim3 qkvGrid(D_MODEL / 128, M_TOKENS / 128, 3);  // (8, 64, 3)
    gemm_tc<<<qkvGrid, 256, GEMM_SMEM>>>(
        xh,
        wqh, wql, wkh, wkl, wvh, wvl,
        nullptr,
        qh, kh, kl, vth, vtl, 1);

    dim3 attnGrid(SEQ / 128, BATCH * NUM_HEADS);     // (16, 64)
    flash_tc<<<attnGrid, 256, FA_SMEM>>>(qh, kh, kl, vth, vtl, oh);

    // Output projection (mode 0)
    dim3 oGrid(D_MODEL / 128, M_TOKENS / 128, 1);    // (8, 64)
    gemm_tc<<<oGrid, 256, GEMM_SMEM>>>(
        oh,
        woh, wol, woh, wol, woh, wol,
        out,
        nullptr, nullptr, nullptr, nullptr, nullptr, 0);
}

// round 16
// speedup vs baseline: 1.7541x; 1.1830x over previous
#include <cuda_runtime.h>
#include <cuda_bf16.h>
#include <cuda_fp16.h>
#include <cstdint>

#define D_MODEL   1024
#define NUM_HEADS 16
#define D_K       64
#define BATCH     4
#define SEQ       2048
#define M_TOKENS  (BATCH * SEQ)          // 8192
#define NELEM     (M_TOKENS * D_MODEL)   // 8388608
#define W_ELEM    (D_MODEL * D_MODEL)    // 1048576

// ---------------------------------------------------------------------------
// Scratch (allocation-free)
// ---------------------------------------------------------------------------
__device__ __half g_xh[NELEM];                         // x plain fp16
__device__ __half g_wqh[W_ELEM], g_wql[W_ELEM];        // weights fp16 hi/lo
__device__ __half g_wkh[W_ELEM], g_wkl[W_ELEM];
__device__ __half g_wvh[W_ELEM], g_wvl[W_ELEM];
__device__ __half g_woh[W_ELEM], g_wol[W_ELEM];
__device__ __half g_qh[NELEM];                         // Q fp16 [b,h,s,d], pre-scaled
__device__ __half g_kh[NELEM];                         // K fp16 [b,h,s,d]
__device__ __half g_vth[NELEM];                        // V fp16 [b,h,d,s] (transposed)
__device__ __half g_oh[NELEM];                         // attn out fp16 [tok,1024]

// ---------------------------------------------------------------------------
// helpers
// ---------------------------------------------------------------------------
__device__ __forceinline__ void mma16816h(float* c, const uint32_t* a,
                                          const uint32_t* b)
{
    asm volatile(
        "mma.sync.aligned.m16n8k16.row.col.f32.f16.f16.f32 "
        "{%0,%1,%2,%3}, {%4,%5,%6,%7}, {%8,%9}, {%0,%1,%2,%3};"
        : "+f"(c[0]), "+f"(c[1]), "+f"(c[2]), "+f"(c[3])
        : "r"(a[0]), "r"(a[1]), "r"(a[2]), "r"(a[3]),
          "r"(b[0]), "r"(b[1]));
}
__device__ __forceinline__ void ldsm_x4(uint32_t& r0, uint32_t& r1,
                                        uint32_t& r2, uint32_t& r3,
                                        uint32_t addr)
{
    asm volatile("ldmatrix.sync.aligned.m8n8.x4.shared.b16 {%0,%1,%2,%3}, [%4];"
                 : "=r"(r0), "=r"(r1), "=r"(r2), "=r"(r3) : "r"(addr));
}
__device__ __forceinline__ uint32_t smem_u32(const void* p) {
    uint32_t a;
    asm("{ .reg .u64 t; cvta.to.shared.u64 t, %1; cvt.u32.u64 %0, t; }"
        : "=r"(a) : "l"(p));
    return a;
}
__device__ __forceinline__ void cp_async16(uint32_t dst, const void* src) {
    asm volatile("cp.async.cg.shared.global [%0], [%1], 16;"
                 :: "r"(dst), "l"(src) : "memory");
}
__device__ __forceinline__ void cp_commit() {
    asm volatile("cp.async.commit_group;" ::: "memory");
}
template <int N>
__device__ __forceinline__ void cp_wait() {
    asm volatile("cp.async.wait_group %0;" :: "n"(N) : "memory");
}
// fp16 hi/lo split (weights only)
__device__ __forceinline__ void split2h(float x, float y,
                                        uint32_t& hi, uint32_t& lo) {
    __half hx = __float2half_rn(x);
    __half hy = __float2half_rn(y);
    __half lx = __float2half_rn(x - __half2float(hx));
    __half ly = __float2half_rn(y - __half2float(hy));
    hi = (uint32_t)__half_as_ushort(hx) |
         ((uint32_t)__half_as_ushort(hy) << 16);
    lo = (uint32_t)__half_as_ushort(lx) |
         ((uint32_t)__half_as_ushort(ly) << 16);
}
__device__ __forceinline__ uint32_t packh2(float x, float y) {
    __half2 t = __floats2half2_rn(x, y);    // x -> low half
    return *reinterpret_cast<uint32_t*>(&t);
}

// ---------------------------------------------------------------------------
// fp32 -> plain fp16 (x)
// ---------------------------------------------------------------------------
__global__ void prep_half(const float* __restrict__ in,
                          __half* __restrict__ out, int n4)
{
    int i = blockIdx.x * blockDim.x + threadIdx.x;
    if (i >= n4) return;
    float4 f = ((const float4*)in)[i];
    uint2 o;
    o.x = packh2(f.x, f.y);
    o.y = packh2(f.z, f.w);
    ((uint2*)out)[i] = o;
}

// All 4 weight matrices -> fp16 hi/lo, one launch: grid (W_ELEM/4/256, 4)
__global__ void prep_split_w4(
    const float* __restrict__ wq, const float* __restrict__ wk,
    const float* __restrict__ wv, const float* __restrict__ wo,
    __half* __restrict__ qh, __half* __restrict__ ql,
    __half* __restrict__ kh, __half* __restrict__ kl,
    __half* __restrict__ vh, __half* __restrict__ vl,
    __half* __restrict__ oh, __half* __restrict__ ol)
{
    int i = blockIdx.x * blockDim.x + threadIdx.x;
    const float* in;
    __half *hi, *lo;
    if      (blockIdx.y == 0) { in = wq; hi = qh; lo = ql; }
    else if (blockIdx.y == 1) { in = wk; hi = kh; lo = kl; }
    else if (blockIdx.y == 2) { in = wv; hi = vh; lo = vl; }
    else                      { in = wo; hi = oh; lo = ol; }
    float4 f = ((const float4*)in)[i];
    uint2 h, l;
    uint32_t h0, l0, h1, l1;
    split2h(f.x, f.y, h0, l0);
    split2h(f.z, f.w, h1, l1);
    h.x = h0; h.y = h1; l.x = l0; l.y = l1;
    ((uint2*)hi)[i] = h;
    ((uint2*)lo)[i] = l;
}

// ---------------------------------------------------------------------------
// HMMA GEMM, fp16 2-product: A plain fp16, B fp16 hi/lo.
// C = A*Bh + A*Bl. CTA 128x128, BK=32, 256 threads, 2 CTAs/SM, ldmatrix.
// fused=1: grid.z in {0,1,2} selects Q/K/V weight + epilogue mode z+1.
// fused=0: output projection, fp32 epilogue (mode 0).
// mode 1: Q -> plain fp16 [b,h,s,d], scaled by 0.125
// mode 2: K -> plain fp16 [b,h,s,d]
// mode 3: V -> plain fp16 [b,h,d,s] (transposed)
// ---------------------------------------------------------------------------
#define BK        32
#define SROW      40
#define TILE_B    (128 * SROW * 2)           // 10240 bytes
#define STAGE_B   (3 * TILE_B)               // A, Bh, Bl = 30720
#define GEMM_SMEM (2 * STAGE_B)              // 61440
#define NK_CHUNKS (D_MODEL / BK)

__global__ __launch_bounds__(256, 2)
void gemm_tc(const __half* __restrict__ A,
             const __half* __restrict__ B0h, const __half* __restrict__ B0l,
             const __half* __restrict__ B1h, const __half* __restrict__ B1l,
             const __half* __restrict__ B2h, const __half* __restrict__ B2l,
             float* __restrict__ C,
             __half* __restrict__ C0, __half* __restrict__ C1,
             __half* __restrict__ C2,
             int fused)
{
    extern __shared__ __align__(16) char sm[];

    const int mode = fused ? ((int)blockIdx.z + 1) : 0;
    const __half *Bhi, *Blo;
    __half *Ch = nullptr;
    if (!fused || blockIdx.z == 0) { Bhi = B0h; Blo = B0l; Ch = C0; }
    else if (blockIdx.z == 1)      { Bhi = B1h; Blo = B1l; Ch = C1; }
    else                           { Bhi = B2h; Blo = B2l; Ch = C2; }

    const int tid  = threadIdx.x;
    const int wid  = tid >> 5;
    const int lane = tid & 31;
    const int grp  = lane >> 2;
    const int qp   = lane & 3;
    const int lrow = lane & 7;
    const int mat  = lane >> 3;

    const int warp_m = (wid & 1) * 64;
    const int warp_n = (wid >> 1) * 32;

    const int a_row = warp_m + (mat & 1) * 8 + lrow;   // + mf*16
    const int a_col = (mat >> 1) * 8;                  // + kb
    const int b_row = warp_n + (mat >> 1) * 8 + lrow;  // + nfp*16
    const int b_col = (mat & 1) * 8;                   // + kb

    const int m0 = blockIdx.y * 128;
    const int n0 = blockIdx.x * 128;

    const __half* srcs[3] = {
        A   + (size_t)m0 * D_MODEL,
        Bhi + (size_t)n0 * D_MODEL,
        Blo + (size_t)n0 * D_MODEL
    };

    const uint32_t smbase = smem_u32(sm);

    auto load_stage = [&](int stage, int k0) {
        uint32_t dst0 = smbase + stage * STAGE_B;
#pragma unroll
        for (int a = 0; a < 3; ++a) {
#pragma unroll
            for (int it = 0; it < 2; ++it) {
                int g   = tid + it * 256;
                int row = g >> 2;
                int q   = g & 3;
                const __half* src = srcs[a] + (size_t)row * D_MODEL + k0 + q * 8;
                cp_async16(dst0 + a * TILE_B + (row * SROW + q * 8) * 2, src);
            }
        }
        cp_commit();
    };

    float acc[4][4][4];
#pragma unroll
    for (int mf = 0; mf < 4; ++mf)
#pragma unroll
        for (int nf = 0; nf < 4; ++nf)
#pragma unroll
            for (int r = 0; r < 4; ++r) acc[mf][nf][r] = 0.0f;

    load_stage(0, 0);
    load_stage(1, BK);

    for (int kc = 0; kc < NK_CHUNKS; ++kc) {
        if (kc < NK_CHUNKS - 2) cp_wait<1>();
        else                    cp_wait<0>();
        __syncthreads();

        const int st = kc & 1;
        const uint32_t a_base  = smbase + st * STAGE_B;
        const uint32_t bh_base = a_base + TILE_B;
        const uint32_t bl_base = a_base + 2 * TILE_B;

#pragma unroll
        for (int ks = 0; ks < 2; ++ks) {
            const int kb = ks * 16;
            uint32_t bhi[4][2], blo[4][2];
#pragma unroll
            for (int nfp = 0; nfp < 2; ++nfp) {
                uint32_t off = (uint32_t)(((b_row + nfp * 16) * SROW + b_col + kb) * 2);
                ldsm_x4(bhi[2*nfp][0], bhi[2*nfp][1],
                        bhi[2*nfp+1][0], bhi[2*nfp+1][1], bh_base + off);
                ldsm_x4(blo[2*nfp][0], blo[2*nfp][1],
                        blo[2*nfp+1][0], blo[2*nfp+1][1], bl_base + off);
            }
#pragma unroll
            for (int mf = 0; mf < 4; ++mf) {
                uint32_t off = (uint32_t)(((a_row + mf * 16) * SROW + a_col + kb) * 2);
                uint32_t ah[4];
                ldsm_x4(ah[0], ah[1], ah[2], ah[3], a_base + off);
#pragma unroll
                for (int nf = 0; nf < 4; ++nf) {
                    mma16816h(acc[mf][nf], ah, bhi[nf]);
                    mma16816h(acc[mf][nf], ah, blo[nf]);
                }
            }
        }
        __syncthreads();
        if (kc + 2 < NK_CHUNKS) load_stage(st, (kc + 2) * BK);
    }

    // Epilogue
    const float scale = (mode == 1) ? 0.125f : 1.0f;
#pragma unroll
    for (int mf = 0; mf < 4; ++mf) {
#pragma unroll
        for (int half = 0; half < 2; ++half) {
            int m = m0 + warp_m + mf * 16 + grp + half * 8;
            int b = m >> 11, s = m & (SEQ - 1);
#pragma unroll
            for (int nf = 0; nf < 4; ++nf) {
                int n = n0 + warp_n + nf * 8 + qp * 2;
                float vx = acc[mf][nf][half * 2] * scale;
                float vy = acc[mf][nf][half * 2 + 1] * scale;
                if (mode == 0) {
                    *(float2*)&C[(size_t)m * D_MODEL + n] = make_float2(vx, vy);
                } else {
                    int h = n >> 6, d = n & 63;
                    if (mode != 3) {
                        size_t base = ((size_t)(b * NUM_HEADS + h) * SEQ + s) * D_K + d;
                        *(uint32_t*)&Ch[base] = packh2(vx, vy);
                    } else {
                        size_t base = ((size_t)(b * NUM_HEADS + h) * D_K + d) * SEQ + s;
                        Ch[base]       = __float2half_rn(vx);
                        Ch[base + SEQ] = __float2half_rn(vy);
                    }
                }
            }
        }
    }
}

// ---------------------------------------------------------------------------
// HMMA flash attention (causal, online softmax, all-plain-fp16 operands,
// fp32 accumulation). 256 threads (8 warps), BM=128, BN=64.
// S = Q*K (1 MMA), O += P*V (1 MMA). B-frags via ldmatrix.x4.
// Reversed query-tile scheduling: heavy (large-i0) CTAs launch first.
// ---------------------------------------------------------------------------
#define FROW     72                         // 64 + 8 pad (fp16)
#define FTILE    (64 * FROW)                // elems per tile
#define FSTAGE   (2 * FTILE)                // K, Vt
#define FA_SMEM  (2 * FSTAGE * 2)           // bytes = 36864

__global__ __launch_bounds__(256, 2)
void flash_tc(const __half* __restrict__ q,
              const __half* __restrict__ k,
              const __half* __restrict__ vt,
              __half* __restrict__ oh)
{
    extern __shared__ __align__(16) __half fsh[];

    const int tid  = threadIdx.x;
    const int w    = tid >> 5;               // 0..7
    const int lane = tid & 31;
    const int grp  = lane >> 2;
    const int qp   = lane & 3;
    const int lrow = lane & 7;
    const int mat  = lane >> 3;

    const int bh = blockIdx.y;
    const int b  = bh >> 4;
    const int h  = bh & 15;
    // Reversed scheduling: heaviest query tiles (largest i0) first.
    const int i0 = ((int)gridDim.x - 1 - (int)blockIdx.x) * 128;

    // ldmatrix per-lane address components for B-frag loads (elements)
    const int b_row = (mat >> 1) * 8 + lrow;   // + nfp*16
    const int b_col = (mat & 1) * 8;           // + kf*16

    // Q fragments (plain fp16, pre-scaled by 0.125)
    uint32_t qhf[4][4];
    {
        const __half* qp0 = q + ((size_t)bh * SEQ + i0 + w * 16) * D_K;
#pragma unroll
        for (int kf = 0; kf < 4; ++kf) {
            int c0 = kf * 16 + qp * 2;
            qhf[kf][0] = *(const uint32_t*)&qp0[grp * D_K + c0];
            qhf[kf][1] = *(const uint32_t*)&qp0[(grp + 8) * D_K + c0];
            qhf[kf][2] = *(const uint32_t*)&qp0[grp * D_K + c0 + 8];
            qhf[kf][3] = *(const uint32_t*)&qp0[(grp + 8) * D_K + c0 + 8];
        }
    }

    const uint32_t smbase = smem_u32(fsh);

    auto load_kv = [&](int stage, int j0) {
        uint32_t dstb = smbase + stage * FSTAGE * 2;
#pragma unroll
        for (int t4 = 0; t4 < 4; ++t4) {
            int c    = tid + t4 * 256;       // 0..1023
            int tile = c >> 9;               // 0: K, 1: Vt
            int idx  = c & 511;
            int row  = idx >> 3;
            int c8   = idx & 7;
            const __half* sp;
            if (tile == 0)
                sp = k  + ((size_t)bh * SEQ + j0 + row) * D_K + c8 * 8;
            else
                sp = vt + ((size_t)bh * D_K + row) * SEQ + j0 + c8 * 8;
            cp_async16(dstb + (tile * FTILE + row * FROW + c8 * 8) * 2, sp);
        }
        cp_commit();
    };

    float oacc[8][4];
#pragma unroll
    for (int nf = 0; nf < 8; ++nf)
#pragma unroll
        for (int r = 0; r < 4; ++r) oacc[nf][r] = 0.0f;
    float m0v = -1e30f, m1v = -1e30f, l0 = 0.0f, l1 = 0.0f;

    const int nt = i0 / 64 + 2;              // key tiles j0 = 0 .. i0+64
    load_kv(0, 0);

    for (int t = 0; t < nt; ++t) {
        const int st = t & 1;
        const int j0 = t * 64;
        if (t + 1 < nt) { load_kv(st ^ 1, (t + 1) * 64); cp_wait<1>(); }
        else            { cp_wait<0>(); }
        __syncthreads();

        const uint32_t kh_base = smbase + st * FSTAGE * 2;
        const uint32_t vh_base = kh_base + FTILE * 2;

        // S = Q K^T (1 MMA per kf,nf), B-frags via ldmatrix
        float sacc[8][4];
#pragma unroll
        for (int nf = 0; nf < 8; ++nf)
#pragma unroll
            for (int r = 0; r < 4; ++r) sacc[nf][r] = 0.0f;

#pragma unroll
        for (int kf = 0; kf < 4; ++kf) {
            const int cc = kf * 16;
#pragma unroll
            for (int half2x = 0; half2x < 2; ++half2x) {   // nfp pairs {0,1},{2,3}
                uint32_t bk[4][2];
#pragma unroll
                for (int p = 0; p < 2; ++p) {
                    int nfp = half2x * 2 + p;
                    uint32_t off = (uint32_t)(((nfp * 16 + b_row) * FROW + b_col + cc) * 2);
                    ldsm_x4(bk[2*p][0], bk[2*p][1],
                            bk[2*p+1][0], bk[2*p+1][1], kh_base + off);
                }
#pragma unroll
                for (int j = 0; j < 4; ++j)
                    mma16816h(sacc[half2x * 4 + j], qhf[kf], bk[j]);
            }
        }

        // causal mask (any tile overlapping this warp's rows; warp-uniform test)
        if (j0 + 64 > i0 + w * 16) {
            const int grow0 = i0 + w * 16 + grp;
#pragma unroll
            for (int nf = 0; nf < 8; ++nf) {
                int gc = j0 + nf * 8 + qp * 2;
                if (gc     > grow0)     sacc[nf][0] = -1e30f;
                if (gc + 1 > grow0)     sacc[nf][1] = -1e30f;
                if (gc     > grow0 + 8) sacc[nf][2] = -1e30f;
                if (gc + 1 > grow0 + 8) sacc[nf][3] = -1e30f;
            }
        }

        // row max (own 16 + quad shfl)
        float mx0 = -1e30f, mx1 = -1e30f;
#pragma unroll
        for (int nf = 0; nf < 8; ++nf) {
            mx0 = fmaxf(mx0, fmaxf(sacc[nf][0], sacc[nf][1]));
            mx1 = fmaxf(mx1, fmaxf(sacc[nf][2], sacc[nf][3]));
        }
        mx0 = fmaxf(mx0, __shfl_xor_sync(0xffffffffu, mx0, 1));
        mx0 = fmaxf(mx0, __shfl_xor_sync(0xffffffffu, mx0, 2));
        mx1 = fmaxf(mx1, __shfl_xor_sync(0xffffffffu, mx1, 1));
        mx1 = fmaxf(mx1, __shfl_xor_sync(0xffffffffu, mx1, 2));

        float mn0 = fmaxf(m0v, mx0), mn1 = fmaxf(m1v, mx1);
        float a0 = __expf(m0v - mn0), a1 = __expf(m1v - mn1);
        m0v = mn0; m1v = mn1;

        // P = exp(S - m), plain fp16, packed as A-fragments
        float s0 = 0.0f, s1 = 0.0f;
        uint32_t ph01[8], ph23[8];
#pragma unroll
        for (int nf = 0; nf < 8; ++nf) {
            float p0 = __expf(sacc[nf][0] - mn0);
            float p1 = __expf(sacc[nf][1] - mn0);
            float p2 = __expf(sacc[nf][2] - mn1);
            float p3 = __expf(sacc[nf][3] - mn1);
            s0 += p0 + p1; s1 += p2 + p3;
            ph01[nf] = packh2(p0, p1);
            ph23[nf] = packh2(p2, p3);
        }
        s0 += __shfl_xor_sync(0xffffffffu, s0, 1);
        s0 += __shfl_xor_sync(0xffffffffu, s0, 2);
        s1 += __shfl_xor_sync(0xffffffffu, s1, 1);
        s1 += __shfl_xor_sync(0xffffffffu, s1, 2);
        l0 = l0 * a0 + s0;
        l1 = l1 * a1 + s1;

#pragma unroll
        for (int nf = 0; nf < 8; ++nf) {
            oacc[nf][0] *= a0; oacc[nf][1] *= a0;
            oacc[nf][2] *= a1; oacc[nf][3] *= a1;
        }

        // O += P V (1 MMA per kf,nfd), V-frags via ldmatrix
#pragma unroll
        for (int kf = 0; kf < 4; ++kf) {
            const int cc = kf * 16;
            uint32_t ap[4] = { ph01[2 * kf], ph23[2 * kf],
                               ph01[2 * kf + 1], ph23[2 * kf + 1] };
#pragma unroll
            for (int half2x = 0; half2x < 2; ++half2x) {
                uint32_t bv[4][2];
#pragma unroll
                for (int p = 0; p < 2; ++p) {
                    int nfp = half2x * 2 + p;
                    uint32_t off = (uint32_t)(((nfp * 16 + b_row) * FROW + b_col + cc) * 2);
                    ldsm_x4(bv[2*p][0], bv[2*p][1],
                            bv[2*p+1][0], bv[2*p+1][1], vh_base + off);
                }
#pragma unroll
                for (int j = 0; j < 4; ++j)
                    mma16816h(oacc[half2x * 4 + j], ap, bv[j]);
            }
        }
        __syncthreads();
    }

    // epilogue: normalize, write plain fp16, merged [tok, h*64+d]
    const float il0 = 1.0f / l0, il1 = 1.0f / l1;
    const size_t tok0 = (size_t)b * SEQ + i0 + w * 16 + grp;
#pragma unroll
    for (int nf = 0; nf < 8; ++nf) {
        int col = h * D_K + nf * 8 + qp * 2;
        *(uint32_t*)&oh[tok0 * D_MODEL + col] =
            packh2(oacc[nf][0] * il0, oacc[nf][1] * il0);
        *(uint32_t*)&oh[(tok0 + 8) * D_MODEL + col] =
            packh2(oacc[nf][2] * il1, oacc[nf][3] * il1);
    }
}

// ---------------------------------------------------------------------------
// Launch
// ---------------------------------------------------------------------------
extern "C" void kernel_launch(void* const* d_in, const int* in_sizes, int n_in,
                              void* d_out, int out_size)
{
    const float* x  = (const float*)d_in[0];
    const float* wq = (const float*)d_in[1];
    const float* wk = (const float*)d_in[2];
    const float* wv = (const float*)d_in[3];
    const float* wo = (const float*)d_in[4];
    float* out = (float*)d_out;

    __half *xh, *wqh, *wql, *wkh, *wkl, *wvh, *wvl, *woh, *wol,
           *qh, *kh, *vth, *oh;
    cudaGetSymbolAddress((void**)&xh, g_xh);
    cudaGetSymbolAddress((void**)&wqh, g_wqh);
    cudaGetSymbolAddress((void**)&wql, g_wql);
    cudaGetSymbolAddress((void**)&wkh, g_wkh);
    cudaGetSymbolAddress((void**)&wkl, g_wkl);
    cudaGetSymbolAddress((void**)&wvh, g_wvh);
    cudaGetSymbolAddress((void**)&wvl, g_wvl);
    cudaGetSymbolAddress((void**)&woh, g_woh);
    cudaGetSymbolAddress((void**)&wol, g_wol);
    cudaGetSymbolAddress((void**)&qh, g_qh);
    cudaGetSymbolAddress((void**)&kh, g_kh);
    cudaGetSymbolAddress((void**)&vth, g_vth);
    cudaGetSymbolAddress((void**)&oh, g_oh);

    cudaFuncSetAttribute(gemm_tc, cudaFuncAttributeMaxDynamicSharedMemorySize,
                         GEMM_SMEM);
    cudaFuncSetAttribute(flash_tc, cudaFuncAttributeMaxDynamicSharedMemorySize,
                         FA_SMEM);

    prep_half<<<NELEM / 4 / 256, 256>>>(x, xh, NELEM / 4);
    dim3 wGrid(W_ELEM / 4 / 256, 4);                 // (1024, 4)
    prep_split_w4<<<wGrid, 256>>>(wq, wk, wv, wo,
                                  wqh, wql, wkh, wkl,
                                  wvh, wvl, woh, wol);

    // Fused Q/K/V projections: grid.z selects weight + epilogue
    dim3 qkvGrid(D_MODEL / 128, M_TOKENS / 128, 3);  // (8, 64, 3)
    gemm_tc<<<qkvGrid, 256, GEMM_SMEM>>>(
        xh,
        wqh, wql, wkh, wkl, wvh, wvl,
        nullptr,
        qh, kh, vth, 1);

    dim3 attnGrid(SEQ / 128, BATCH * NUM_HEADS);     // (16, 64)
    flash_tc<<<attnGrid, 256, FA_SMEM>>>(qh, kh, vth, oh);

    // Output projection (mode 0)
    dim3 oGrid(D_MODEL / 128, M_TOKENS / 128, 1);    // (8, 64)
    gemm_tc<<<oGrid, 256, GEMM_SMEM>>>(
        oh,
        woh, wol, woh, wol, woh, wol,
        out,
        nullptr, nullptr, nullptr, 0);
}

// round 17
// speedup vs baseline: 2.3849x; 1.3596x over previous
#include <cuda_runtime.h>
#include <cuda_bf16.h>
#include <cuda_fp16.h>
#include <cstdint>

#define D_MODEL   1024
#define NUM_HEADS 16
#define D_K       64
#define BATCH     4
#define SEQ       2048
#define M_TOKENS  (BATCH * SEQ)          // 8192
#define NELEM     (M_TOKENS * D_MODEL)   // 8388608
#define W_ELEM    (D_MODEL * D_MODEL)    // 1048576

// ---------------------------------------------------------------------------
// Scratch (allocation-free)
// ---------------------------------------------------------------------------
__device__ __half g_xh[NELEM];                         // x plain fp16
__device__ __half g_wq[W_ELEM], g_wk[W_ELEM];          // weights plain fp16
__device__ __half g_wv[W_ELEM], g_wo[W_ELEM];
__device__ __half g_qh[NELEM];                         // Q fp16 [b,h,s,d], pre-scaled
__device__ __half g_kh[NELEM];                         // K fp16 [b,h,s,d]
__device__ __half g_vth[NELEM];                        // V fp16 [b,h,d,s] (transposed)
__device__ __half g_oh[NELEM];                         // attn out fp16 [tok,1024]

// ---------------------------------------------------------------------------
// helpers
// ---------------------------------------------------------------------------
__device__ __forceinline__ void mma16816h(float* c, const uint32_t* a,
                                          const uint32_t* b)
{
    asm volatile(
        "mma.sync.aligned.m16n8k16.row.col.f32.f16.f16.f32 "
        "{%0,%1,%2,%3}, {%4,%5,%6,%7}, {%8,%9}, {%0,%1,%2,%3};"
        : "+f"(c[0]), "+f"(c[1]), "+f"(c[2]), "+f"(c[3])
        : "r"(a[0]), "r"(a[1]), "r"(a[2]), "r"(a[3]),
          "r"(b[0]), "r"(b[1]));
}
__device__ __forceinline__ void ldsm_x4(uint32_t& r0, uint32_t& r1,
                                        uint32_t& r2, uint32_t& r3,
                                        uint32_t addr)
{
    asm volatile("ldmatrix.sync.aligned.m8n8.x4.shared.b16 {%0,%1,%2,%3}, [%4];"
                 : "=r"(r0), "=r"(r1), "=r"(r2), "=r"(r3) : "r"(addr));
}
__device__ __forceinline__ uint32_t smem_u32(const void* p) {
    uint32_t a;
    asm("{ .reg .u64 t; cvta.to.shared.u64 t, %1; cvt.u32.u64 %0, t; }"
        : "=r"(a) : "l"(p));
    return a;
}
__device__ __forceinline__ void cp_async16(uint32_t dst, const void* src) {
    asm volatile("cp.async.cg.shared.global [%0], [%1], 16;"
                 :: "r"(dst), "l"(src) : "memory");
}
__device__ __forceinline__ void cp_commit() {
    asm volatile("cp.async.commit_group;" ::: "memory");
}
template <int N>
__device__ __forceinline__ void cp_wait() {
    asm volatile("cp.async.wait_group %0;" :: "n"(N) : "memory");
}
__device__ __forceinline__ uint32_t packh2(float x, float y) {
    __half2 t = __floats2half2_rn(x, y);    // x -> low half
    return *reinterpret_cast<uint32_t*>(&t);
}

// ---------------------------------------------------------------------------
// fp32 -> plain fp16 (x)
// ---------------------------------------------------------------------------
__global__ void prep_half(const float* __restrict__ in,
                          __half* __restrict__ out, int n4)
{
    int i = blockIdx.x * blockDim.x + threadIdx.x;
    if (i >= n4) return;
    float4 f = ((const float4*)in)[i];
    uint2 o;
    o.x = packh2(f.x, f.y);
    o.y = packh2(f.z, f.w);
    ((uint2*)out)[i] = o;
}

// All 4 weight matrices -> plain fp16, one launch: grid (W_ELEM/4/256, 4)
__global__ void prep_half_w4(
    const float* __restrict__ wq, const float* __restrict__ wk,
    const float* __restrict__ wv, const float* __restrict__ wo,
    __half* __restrict__ oq, __half* __restrict__ ok,
    __half* __restrict__ ov, __half* __restrict__ oo)
{
    int i = blockIdx.x * blockDim.x + threadIdx.x;
    const float* in;
    __half* out;
    if      (blockIdx.y == 0) { in = wq; out = oq; }
    else if (blockIdx.y == 1) { in = wk; out = ok; }
    else if (blockIdx.y == 2) { in = wv; out = ov; }
    else                      { in = wo; out = oo; }
    float4 f = ((const float4*)in)[i];
    uint2 o;
    o.x = packh2(f.x, f.y);
    o.y = packh2(f.z, f.w);
    ((uint2*)out)[i] = o;
}

// ---------------------------------------------------------------------------
// HMMA GEMM, all-plain fp16 (1 MMA per fragment pair), fp32 accumulate.
// CTA 128x128, BK=32, 256 threads, 2 CTAs/SM, ldmatrix.
// fused=1: grid.z in {0,1,2} selects Q/K/V weight + epilogue mode z+1.
// fused=0: output projection, fp32 epilogue (mode 0).
// mode 1: Q -> plain fp16 [b,h,s,d], scaled by 0.125
// mode 2: K -> plain fp16 [b,h,s,d]
// mode 3: V -> plain fp16 [b,h,d,s] (transposed)
// ---------------------------------------------------------------------------
#define BK        32
#define SROW      40
#define TILE_B    (128 * SROW * 2)           // 10240 bytes
#define STAGE_B   (2 * TILE_B)               // A, B = 20480
#define GEMM_SMEM (2 * STAGE_B)              // 40960
#define NK_CHUNKS (D_MODEL / BK)

__global__ __launch_bounds__(256, 2)
void gemm_tc(const __half* __restrict__ A,
             const __half* __restrict__ B0, const __half* __restrict__ B1,
             const __half* __restrict__ B2,
             float* __restrict__ C,
             __half* __restrict__ C0, __half* __restrict__ C1,
             __half* __restrict__ C2,
             int fused)
{
    extern __shared__ __align__(16) char sm[];

    const int mode = fused ? ((int)blockIdx.z + 1) : 0;
    const __half* B;
    __half* Ch = nullptr;
    if (!fused || blockIdx.z == 0) { B = B0; Ch = C0; }
    else if (blockIdx.z == 1)      { B = B1; Ch = C1; }
    else                           { B = B2; Ch = C2; }

    const int tid  = threadIdx.x;
    const int wid  = tid >> 5;
    const int lane = tid & 31;
    const int grp  = lane >> 2;
    const int qp   = lane & 3;
    const int lrow = lane & 7;
    const int mat  = lane >> 3;

    const int warp_m = (wid & 1) * 64;
    const int warp_n = (wid >> 1) * 32;

    const int a_row = warp_m + (mat & 1) * 8 + lrow;   // + mf*16
    const int a_col = (mat >> 1) * 8;                  // + kb
    const int b_row = warp_n + (mat >> 1) * 8 + lrow;  // + nfp*16
    const int b_col = (mat & 1) * 8;                   // + kb

    const int m0 = blockIdx.y * 128;
    const int n0 = blockIdx.x * 128;

    const __half* srcs[2] = {
        A + (size_t)m0 * D_MODEL,
        B + (size_t)n0 * D_MODEL
    };

    const uint32_t smbase = smem_u32(sm);

    auto load_stage = [&](int stage, int k0) {
        uint32_t dst0 = smbase + stage * STAGE_B;
#pragma unroll
        for (int a = 0; a < 2; ++a) {
#pragma unroll
            for (int it = 0; it < 2; ++it) {
                int g   = tid + it * 256;
                int row = g >> 2;
                int q   = g & 3;
                const __half* src = srcs[a] + (size_t)row * D_MODEL + k0 + q * 8;
                cp_async16(dst0 + a * TILE_B + (row * SROW + q * 8) * 2, src);
            }
        }
        cp_commit();
    };

    float acc[4][4][4];
#pragma unroll
    for (int mf = 0; mf < 4; ++mf)
#pragma unroll
        for (int nf = 0; nf < 4; ++nf)
#pragma unroll
            for (int r = 0; r < 4; ++r) acc[mf][nf][r] = 0.0f;

    load_stage(0, 0);
    load_stage(1, BK);

    for (int kc = 0; kc < NK_CHUNKS; ++kc) {
        if (kc < NK_CHUNKS - 2) cp_wait<1>();
        else                    cp_wait<0>();
        __syncthreads();

        const int st = kc & 1;
        const uint32_t a_base = smbase + st * STAGE_B;
        const uint32_t b_base = a_base + TILE_B;

#pragma unroll
        for (int ks = 0; ks < 2; ++ks) {
            const int kb = ks * 16;
            uint32_t bf[4][2];
#pragma unroll
            for (int nfp = 0; nfp < 2; ++nfp) {
                uint32_t off = (uint32_t)(((b_row + nfp * 16) * SROW + b_col + kb) * 2);
                ldsm_x4(bf[2*nfp][0], bf[2*nfp][1],
                        bf[2*nfp+1][0], bf[2*nfp+1][1], b_base + off);
            }
#pragma unroll
            for (int mf = 0; mf < 4; ++mf) {
                uint32_t off = (uint32_t)(((a_row + mf * 16) * SROW + a_col + kb) * 2);
                uint32_t ah[4];
                ldsm_x4(ah[0], ah[1], ah[2], ah[3], a_base + off);
#pragma unroll
                for (int nf = 0; nf < 4; ++nf)
                    mma16816h(acc[mf][nf], ah, bf[nf]);
            }
        }
        __syncthreads();
        if (kc + 2 < NK_CHUNKS) load_stage(st, (kc + 2) * BK);
    }

    // Epilogue
    const float scale = (mode == 1) ? 0.125f : 1.0f;
#pragma unroll
    for (int mf = 0; mf < 4; ++mf) {
#pragma unroll
        for (int half = 0; half < 2; ++half) {
            int m = m0 + warp_m + mf * 16 + grp + half * 8;
            int b = m >> 11, s = m & (SEQ - 1);
#pragma unroll
            for (int nf = 0; nf < 4; ++nf) {
                int n = n0 + warp_n + nf * 8 + qp * 2;
                float vx = acc[mf][nf][half * 2] * scale;
                float vy = acc[mf][nf][half * 2 + 1] * scale;
                if (mode == 0) {
                    *(float2*)&C[(size_t)m * D_MODEL + n] = make_float2(vx, vy);
                } else {
                    int h = n >> 6, d = n & 63;
                    if (mode != 3) {
                        size_t base = ((size_t)(b * NUM_HEADS + h) * SEQ + s) * D_K + d;
                        *(uint32_t*)&Ch[base] = packh2(vx, vy);
                    } else {
                        size_t base = ((size_t)(b * NUM_HEADS + h) * D_K + d) * SEQ + s;
                        Ch[base]       = __float2half_rn(vx);
                        Ch[base + SEQ] = __float2half_rn(vy);
                    }
                }
            }
        }
    }
}

// ---------------------------------------------------------------------------
// HMMA flash attention (causal, online softmax, all-plain-fp16 operands,
// fp32 accumulation). 256 threads (8 warps), BM=128, BN=64.
// S = Q*K (1 MMA), O += P*V (1 MMA). B-frags via ldmatrix.x4.
// Reversed query-tile scheduling: heavy (large-i0) CTAs launch first.
// Unchanged from round 16.
// ---------------------------------------------------------------------------
#define FROW     72                         // 64 + 8 pad (fp16)
#define FTILE    (64 * FROW)                // elems per tile
#define FSTAGE   (2 * FTILE)                // K, Vt
#define FA_SMEM  (2 * FSTAGE * 2)           // bytes = 36864

__global__ __launch_bounds__(256, 2)
void flash_tc(const __half* __restrict__ q,
              const __half* __restrict__ k,
              const __half* __restrict__ vt,
              __half* __restrict__ oh)
{
    extern __shared__ __align__(16) __half fsh[];

    const int tid  = threadIdx.x;
    const int w    = tid >> 5;               // 0..7
    const int lane = tid & 31;
    const int grp  = lane >> 2;
    const int qp   = lane & 3;
    const int lrow = lane & 7;
    const int mat  = lane >> 3;

    const int bh = blockIdx.y;
    const int b  = bh >> 4;
    const int h  = bh & 15;
    // Reversed scheduling: heaviest query tiles (largest i0) first.
    const int i0 = ((int)gridDim.x - 1 - (int)blockIdx.x) * 128;

    // ldmatrix per-lane address components for B-frag loads (elements)
    const int b_row = (mat >> 1) * 8 + lrow;   // + nfp*16
    const int b_col = (mat & 1) * 8;           // + kf*16

    // Q fragments (plain fp16, pre-scaled by 0.125)
    uint32_t qhf[4][4];
    {
        const __half* qp0 = q + ((size_t)bh * SEQ + i0 + w * 16) * D_K;
#pragma unroll
        for (int kf = 0; kf < 4; ++kf) {
            int c0 = kf * 16 + qp * 2;
            qhf[kf][0] = *(const uint32_t*)&qp0[grp * D_K + c0];
            qhf[kf][1] = *(const uint32_t*)&qp0[(grp + 8) * D_K + c0];
            qhf[kf][2] = *(const uint32_t*)&qp0[grp * D_K + c0 + 8];
            qhf[kf][3] = *(const uint32_t*)&qp0[(grp + 8) * D_K + c0 + 8];
        }
    }

    const uint32_t smbase = smem_u32(fsh);

    auto load_kv = [&](int stage, int j0) {
        uint32_t dstb = smbase + stage * FSTAGE * 2;
#pragma unroll
        for (int t4 = 0; t4 < 4; ++t4) {
            int c    = tid + t4 * 256;       // 0..1023
            int tile = c >> 9;               // 0: K, 1: Vt
            int idx  = c & 511;
            int row  = idx >> 3;
            int c8   = idx & 7;
            const __half* sp;
            if (tile == 0)
                sp = k  + ((size_t)bh * SEQ + j0 + row) * D_K + c8 * 8;
            else
                sp = vt + ((size_t)bh * D_K + row) * SEQ + j0 + c8 * 8;
            cp_async16(dstb + (tile * FTILE + row * FROW + c8 * 8) * 2, sp);
        }
        cp_commit();
    };

    float oacc[8][4];
#pragma unroll
    for (int nf = 0; nf < 8; ++nf)
#pragma unroll
        for (int r = 0; r < 4; ++r) oacc[nf][r] = 0.0f;
    float m0v = -1e30f, m1v = -1e30f, l0 = 0.0f, l1 = 0.0f;

    const int nt = i0 / 64 + 2;              // key tiles j0 = 0 .. i0+64
    load_kv(0, 0);

    for (int t = 0; t < nt; ++t) {
        const int st = t & 1;
        const int j0 = t * 64;
        if (t + 1 < nt) { load_kv(st ^ 1, (t + 1) * 64); cp_wait<1>(); }
        else            { cp_wait<0>(); }
        __syncthreads();

        const uint32_t kh_base = smbase + st * FSTAGE * 2;
        const uint32_t vh_base = kh_base + FTILE * 2;

        // S = Q K^T (1 MMA per kf,nf), B-frags via ldmatrix
        float sacc[8][4];
#pragma unroll
        for (int nf = 0; nf < 8; ++nf)
#pragma unroll
            for (int r = 0; r < 4; ++r) sacc[nf][r] = 0.0f;

#pragma unroll
        for (int kf = 0; kf < 4; ++kf) {
            const int cc = kf * 16;
#pragma unroll
            for (int half2x = 0; half2x < 2; ++half2x) {   // nfp pairs {0,1},{2,3}
                uint32_t bk[4][2];
#pragma unroll
                for (int p = 0; p < 2; ++p) {
                    int nfp = half2x * 2 + p;
                    uint32_t off = (uint32_t)(((nfp * 16 + b_row) * FROW + b_col + cc) * 2);
                    ldsm_x4(bk[2*p][0], bk[2*p][1],
                            bk[2*p+1][0], bk[2*p+1][1], kh_base + off);
                }
#pragma unroll
                for (int j = 0; j < 4; ++j)
                    mma16816h(sacc[half2x * 4 + j], qhf[kf], bk[j]);
            }
        }

        // causal mask (any tile overlapping this warp's rows; warp-uniform test)
        if (j0 + 64 > i0 + w * 16) {
            const int grow0 = i0 + w * 16 + grp;
#pragma unroll
            for (int nf = 0; nf < 8; ++nf) {
                int gc = j0 + nf * 8 + qp * 2;
                if (gc     > grow0)     sacc[nf][0] = -1e30f;
                if (gc + 1 > grow0)     sacc[nf][1] = -1e30f;
                if (gc     > grow0 + 8) sacc[nf][2] = -1e30f;
                if (gc + 1 > grow0 + 8) sacc[nf][3] = -1e30f;
            }
        }

        // row max (own 16 + quad shfl)
        float mx0 = -1e30f, mx1 = -1e30f;
#pragma unroll
        for (int nf = 0; nf < 8; ++nf) {
            mx0 = fmaxf(mx0, fmaxf(sacc[nf][0], sacc[nf][1]));
            mx1 = fmaxf(mx1, fmaxf(sacc[nf][2], sacc[nf][3]));
        }
        mx0 = fmaxf(mx0, __shfl_xor_sync(0xffffffffu, mx0, 1));
        mx0 = fmaxf(mx0, __shfl_xor_sync(0xffffffffu, mx0, 2));
        mx1 = fmaxf(mx1, __shfl_xor_sync(0xffffffffu, mx1, 1));
        mx1 = fmaxf(mx1, __shfl_xor_sync(0xffffffffu, mx1, 2));

        float mn0 = fmaxf(m0v, mx0), mn1 = fmaxf(m1v, mx1);
        float a0 = __expf(m0v - mn0), a1 = __expf(m1v - mn1);
        m0v = mn0; m1v = mn1;

        // P = exp(S - m), plain fp16, packed as A-fragments
        float s0 = 0.0f, s1 = 0.0f;
        uint32_t ph01[8], ph23[8];
#pragma unroll
        for (int nf = 0; nf < 8; ++nf) {
            float p0 = __expf(sacc[nf][0] - mn0);
            float p1 = __expf(sacc[nf][1] - mn0);
            float p2 = __expf(sacc[nf][2] - mn1);
            float p3 = __expf(sacc[nf][3] - mn1);
            s0 += p0 + p1; s1 += p2 + p3;
            ph01[nf] = packh2(p0, p1);
            ph23[nf] = packh2(p2, p3);
        }
        s0 += __shfl_xor_sync(0xffffffffu, s0, 1);
        s0 += __shfl_xor_sync(0xffffffffu, s0, 2);
        s1 += __shfl_xor_sync(0xffffffffu, s1, 1);
        s1 += __shfl_xor_sync(0xffffffffu, s1, 2);
        l0 = l0 * a0 + s0;
        l1 = l1 * a1 + s1;

#pragma unroll
        for (int nf = 0; nf < 8; ++nf) {
            oacc[nf][0] *= a0; oacc[nf][1] *= a0;
            oacc[nf][2] *= a1; oacc[nf][3] *= a1;
        }

        // O += P V (1 MMA per kf,nfd), V-frags via ldmatrix
#pragma unroll
        for (int kf = 0; kf < 4; ++kf) {
            const int cc = kf * 16;
            uint32_t ap[4] = { ph01[2 * kf], ph23[2 * kf],
                               ph01[2 * kf + 1], ph23[2 * kf + 1] };
#pragma unroll
            for (int half2x = 0; half2x < 2; ++half2x) {
                uint32_t bv[4][2];
#pragma unroll
                for (int p = 0; p < 2; ++p) {
                    int nfp = half2x * 2 + p;
                    uint32_t off = (uint32_t)(((nfp * 16 + b_row) * FROW + b_col + cc) * 2);
                    ldsm_x4(bv[2*p][0], bv[2*p][1],
                            bv[2*p+1][0], bv[2*p+1][1], vh_base + off);
                }
#pragma unroll
                for (int j = 0; j < 4; ++j)
                    mma16816h(oacc[half2x * 4 + j], ap, bv[j]);
            }
        }
        __syncthreads();
    }

    // epilogue: normalize, write plain fp16, merged [tok, h*64+d]
    const float il0 = 1.0f / l0, il1 = 1.0f / l1;
    const size_t tok0 = (size_t)b * SEQ + i0 + w * 16 + grp;
#pragma unroll
    for (int nf = 0; nf < 8; ++nf) {
        int col = h * D_K + nf * 8 + qp * 2;
        *(uint32_t*)&oh[tok0 * D_MODEL + col] =
            packh2(oacc[nf][0] * il0, oacc[nf][1] * il0);
        *(uint32_t*)&oh[(tok0 + 8) * D_MODEL + col] =
            packh2(oacc[nf][2] * il1, oacc[nf][3] * il1);
    }
}

// ---------------------------------------------------------------------------
// Launch
// ---------------------------------------------------------------------------
extern "C" void kernel_launch(void* const* d_in, const int* in_sizes, int n_in,
                              void* d_out, int out_size)
{
    const float* x  = (const float*)d_in[0];
    const float* wq = (const float*)d_in[1];
    const float* wk = (const float*)d_in[2];
    const float* wv = (const float*)d_in[3];
    const float* wo = (const float*)d_in[4];
    float* out = (float*)d_out;

    __half *xh, *wqp, *wkp, *wvp, *wop, *qh, *kh, *vth, *oh;
    cudaGetSymbolAddress((void**)&xh, g_xh);
    cudaGetSymbolAddress((void**)&wqp, g_wq);
    cudaGetSymbolAddress((void**)&wkp, g_wk);
    cudaGetSymbolAddress((void**)&wvp, g_wv);
    cudaGetSymbolAddress((void**)&wop, g_wo);
    cudaGetSymbolAddress((void**)&qh, g_qh);
    cudaGetSymbolAddress((void**)&kh, g_kh);
    cudaGetSymbolAddress((void**)&vth, g_vth);
    cudaGetSymbolAddress((void**)&oh, g_oh);

    cudaFuncSetAttribute(gemm_tc, cudaFuncAttributeMaxDynamicSharedMemorySize,
                         GEMM_SMEM);
    cudaFuncSetAttribute(flash_tc, cudaFuncAttributeMaxDynamicSharedMemorySize,
                         FA_SMEM);

    prep_half<<<NELEM / 4 / 256, 256>>>(x, xh, NELEM / 4);
    dim3 wGrid(W_ELEM / 4 / 256, 4);                 // (1024, 4)
    prep_half_w4<<<wGrid, 256>>>(wq, wk, wv, wo, wqp, wkp, wvp, wop);

    // Fused Q/K/V projections: grid.z selects weight + epilogue
    dim3 qkvGrid(D_MODEL / 128, M_TOKENS / 128, 3);  // (8, 64, 3)
    gemm_tc<<<qkvGrid, 256, GEMM_SMEM>>>(
        xh, wqp, wkp, wvp,
        nullptr,
        qh, kh, vth, 1);

    dim3 attnGrid(SEQ / 128, BATCH * NUM_HEADS);     // (16, 64)
    flash_tc<<<attnGrid, 256, FA_SMEM>>>(qh, kh, vth, oh);

    // Output projection (mode 0)
    dim3 oGrid(D_MODEL / 128, M_TOKENS / 128, 1);    // (8, 64)
    gemm_tc<<<oGrid, 256, GEMM_SMEM>>>(
        oh, wop, wop, wop,
        out,
        nullptr, nullptr, nullptr, 0);
}